// round 2
// baseline (speedup 1.0000x reference)
#include <cuda_runtime.h>
#include <cuda_bf16.h>

#define Bn  4
#define Qn  2048
#define Kn  2048
#define Dn  1024
#define Hn  16
#define DHn 64
#define BHn (Bn*Hn)

// Scratch (static device allocations are allowed; cudaMalloc is not)
__device__ float g_q[(size_t)BHn*Qn*DHn];   // (b*H+h, q, d)
__device__ float g_k[(size_t)BHn*Kn*DHn];   // (b*H+h, k, d)
__device__ float g_v[(size_t)BHn*Kn*DHn];   // (b*H+h, k, d)
__device__ float g_o[(size_t)Bn*Qn*Hn*DHn]; // (b, q, h*64+d)  -> A operand of out GEMM

// ---------------------------------------------------------------------------
// GEMM tiles: 128x128x16, 256 threads, 8x8 per thread
// ---------------------------------------------------------------------------
#define BM 128
#define BN 128
#define BK 16

__global__ __launch_bounds__(256, 2)
void qkv_gemm(const float* __restrict__ x,
              const float* __restrict__ Wq,
              const float* __restrict__ Wk,
              const float* __restrict__ Wv)
{
    __shared__ float As[BK][BM];
    __shared__ float Bs[BK][BN];

    const int bn = blockIdx.x;       // 0..23 over N=3072
    const int bm = blockIdx.y;       // 0..63 over M=8192
    const int n_base = bn * BN;

    const float* W;
    float* dst;
    if (n_base < 1024)      { W = Wq; dst = g_q; }
    else if (n_base < 2048) { W = Wk; dst = g_k; }
    else                    { W = Wv; dst = g_v; }
    const int col_base = n_base & 1023;

    const int tid = threadIdx.x;
    const int ty = tid >> 4;   // 0..15
    const int tx = tid & 15;   // 0..15
    const int m0 = bm * BM;

    float acc[8][8];
    #pragma unroll
    for (int i = 0; i < 8; i++)
        #pragma unroll
        for (int j = 0; j < 8; j++) acc[i][j] = 0.f;

    for (int k0 = 0; k0 < Dn; k0 += BK) {
        #pragma unroll
        for (int f = 0; f < 2; f++) {
            int fid = tid * 2 + f;          // 0..511
            int row = fid >> 2;             // 0..127
            int c4  = (fid & 3) << 2;       // 0,4,8,12
            float4 v = *(const float4*)&x[(size_t)(m0 + row) * Dn + k0 + c4];
            As[c4+0][row] = v.x; As[c4+1][row] = v.y;
            As[c4+2][row] = v.z; As[c4+3][row] = v.w;
        }
        #pragma unroll
        for (int f = 0; f < 2; f++) {
            int fid = tid * 2 + f;          // 0..511
            int row = fid >> 5;             // 0..15
            int c4  = (fid & 31) << 2;      // 0..124
            *(float4*)&Bs[row][c4] =
                *(const float4*)&W[(size_t)(k0 + row) * 1024 + col_base + c4];
        }
        __syncthreads();

        #pragma unroll
        for (int k = 0; k < BK; k++) {
            float a[8], b[8];
            *(float4*)&a[0] = *(float4*)&As[k][ty*8];
            *(float4*)&a[4] = *(float4*)&As[k][ty*8+4];
            *(float4*)&b[0] = *(float4*)&Bs[k][tx*8];
            *(float4*)&b[4] = *(float4*)&Bs[k][tx*8+4];
            #pragma unroll
            for (int i = 0; i < 8; i++)
                #pragma unroll
                for (int j = 0; j < 8; j++)
                    acc[i][j] += a[i] * b[j];
        }
        __syncthreads();
    }

    // Scatter into (b*H+h, seq, d) layout
    #pragma unroll
    for (int i = 0; i < 8; i++) {
        int m  = m0 + ty*8 + i;
        int bb = m >> 11;           // batch
        int qp = m & 2047;          // position
        #pragma unroll
        for (int j = 0; j < 8; j++) {
            int n = col_base + tx*8 + j;
            int h = n >> 6, d = n & 63;
            dst[(((size_t)(bb*Hn + h))*Qn + qp)*DHn + d] = acc[i][j];
        }
    }
}

__global__ __launch_bounds__(256, 2)
void out_gemm(const float* __restrict__ Wo,
              const float* __restrict__ bo,
              float* __restrict__ out)
{
    __shared__ float As[BK][BM];
    __shared__ float Bs[BK][BN];

    const int bn = blockIdx.x;       // 0..7 over N=1024
    const int bm = blockIdx.y;       // 0..63 over M=8192
    const int n_base = bn * BN;

    const int tid = threadIdx.x;
    const int ty = tid >> 4;
    const int tx = tid & 15;
    const int m0 = bm * BM;

    float acc[8][8];
    #pragma unroll
    for (int i = 0; i < 8; i++)
        #pragma unroll
        for (int j = 0; j < 8; j++) acc[i][j] = 0.f;

    for (int k0 = 0; k0 < 1024; k0 += BK) {
        #pragma unroll
        for (int f = 0; f < 2; f++) {
            int fid = tid * 2 + f;
            int row = fid >> 2;
            int c4  = (fid & 3) << 2;
            float4 v = *(const float4*)&g_o[(size_t)(m0 + row) * 1024 + k0 + c4];
            As[c4+0][row] = v.x; As[c4+1][row] = v.y;
            As[c4+2][row] = v.z; As[c4+3][row] = v.w;
        }
        #pragma unroll
        for (int f = 0; f < 2; f++) {
            int fid = tid * 2 + f;
            int row = fid >> 5;
            int c4  = (fid & 31) << 2;
            *(float4*)&Bs[row][c4] =
                *(const float4*)&Wo[(size_t)(k0 + row) * 1024 + n_base + c4];
        }
        __syncthreads();

        #pragma unroll
        for (int k = 0; k < BK; k++) {
            float a[8], b[8];
            *(float4*)&a[0] = *(float4*)&As[k][ty*8];
            *(float4*)&a[4] = *(float4*)&As[k][ty*8+4];
            *(float4*)&b[0] = *(float4*)&Bs[k][tx*8];
            *(float4*)&b[4] = *(float4*)&Bs[k][tx*8+4];
            #pragma unroll
            for (int i = 0; i < 8; i++)
                #pragma unroll
                for (int j = 0; j < 8; j++)
                    acc[i][j] += a[i] * b[j];
        }
        __syncthreads();
    }

    #pragma unroll
    for (int i = 0; i < 8; i++) {
        int m = m0 + ty*8 + i;
        #pragma unroll
        for (int j = 0; j < 8; j++) {
            int n = n_base + tx*8 + j;
            out[(size_t)m * 1024 + n] = acc[i][j] + bo[n];
        }
    }
}

// ---------------------------------------------------------------------------
// Flash attention, fp32. One block: 128 queries of one (b,h); KV tiles of 64.
// 256 threads: thread (tq=tid/16, tk=tid%16) owns 8 q-rows x 4 cols.
// Mask is int32 (harness materializes JAX bool as int32).
// ---------------------------------------------------------------------------
#define AQ 128
#define AK 64
#define QS_STRIDE 132
#define KS_STRIDE 68
#define PS_STRIDE 68
// floats: Qs 64*132 + Ks 64*68 + Vs 64*68 + Ps 128*68 + 3*128
#define ATTN_SMEM_FLOATS (64*QS_STRIDE + 64*KS_STRIDE + 64*KS_STRIDE + 128*PS_STRIDE + 384)
#define ATTN_SMEM_BYTES (ATTN_SMEM_FLOATS * 4)

__global__ __launch_bounds__(256, 2)
void attn_kernel(const int* __restrict__ mask)
{
    extern __shared__ float sm[];
    float* Qs   = sm;                        // [d][r] transposed, 64 x 132
    float* Ks   = Qs + 64*QS_STRIDE;         // [d][c] transposed, 64 x 68
    float* Vs   = Ks + 64*KS_STRIDE;         // [k][dh], 64 x 68
    float* Ps   = Vs + 64*KS_STRIDE;         // [r][c], 128 x 68
    float* rowm = Ps + 128*PS_STRIDE;        // [128]
    float* rowl = rowm + 128;                // [128]
    float* rowa = rowl + 128;                // [128]

    const int tid = threadIdx.x;
    const int bh  = blockIdx.y;              // 0..63
    const int qt  = blockIdx.x;              // 0..15
    const int b   = bh >> 4;
    const int h   = bh & 15;
    const int q0  = qt * AQ;

    const float* qptr = g_q + (size_t)bh*Qn*DHn + (size_t)q0*DHn;
    const float* kptr = g_k + (size_t)bh*Kn*DHn;
    const float* vptr = g_v + (size_t)bh*Kn*DHn;

    // Load Q tile, transposed to [d][r]
    for (int f = tid; f < AQ*16; f += 256) {
        int r  = f >> 4;
        int d4 = (f & 15) << 2;
        float4 v = *(const float4*)&qptr[(size_t)r*DHn + d4];
        Qs[(d4+0)*QS_STRIDE + r] = v.x;
        Qs[(d4+1)*QS_STRIDE + r] = v.y;
        Qs[(d4+2)*QS_STRIDE + r] = v.z;
        Qs[(d4+3)*QS_STRIDE + r] = v.w;
    }
    if (tid < 128) { rowm[tid] = -1e30f; rowl[tid] = 0.f; }
    __syncthreads();

    const int tq = tid >> 4;    // 0..15  -> rows tq*8..tq*8+7
    const int tk = tid & 15;    // 0..15  -> cols tk*4..tk*4+3

    float o[8][4];
    #pragma unroll
    for (int i = 0; i < 8; i++)
        #pragma unroll
        for (int j = 0; j < 4; j++) o[i][j] = 0.f;

    const size_t mrow_base = ((size_t)b*Qn + q0) * Kn;   // element index into int32 mask

    for (int kt = 0; kt < Kn; kt += AK) {
        // Load K (transposed) + V tiles
        for (int f = tid; f < AK*16; f += 256) {
            int r  = f >> 4;
            int d4 = (f & 15) << 2;
            float4 kv = *(const float4*)&kptr[(size_t)(kt + r)*DHn + d4];
            Ks[(d4+0)*KS_STRIDE + r] = kv.x;
            Ks[(d4+1)*KS_STRIDE + r] = kv.y;
            Ks[(d4+2)*KS_STRIDE + r] = kv.z;
            Ks[(d4+3)*KS_STRIDE + r] = kv.w;
            float4 vv = *(const float4*)&vptr[(size_t)(kt + r)*DHn + d4];
            *(float4*)&Vs[r*KS_STRIDE + d4] = vv;
        }
        __syncthreads();

        // S = Q K^T (8x4 per thread)
        float s[8][4];
        #pragma unroll
        for (int i = 0; i < 8; i++)
            #pragma unroll
            for (int j = 0; j < 4; j++) s[i][j] = 0.f;

        #pragma unroll 8
        for (int d = 0; d < 64; d++) {
            float4 qa = *(const float4*)&Qs[d*QS_STRIDE + tq*8];
            float4 qb = *(const float4*)&Qs[d*QS_STRIDE + tq*8 + 4];
            float4 kc = *(const float4*)&Ks[d*KS_STRIDE + tk*4];
            float qv[8] = {qa.x,qa.y,qa.z,qa.w,qb.x,qb.y,qb.z,qb.w};
            #pragma unroll
            for (int i = 0; i < 8; i++) {
                s[i][0] += qv[i]*kc.x;
                s[i][1] += qv[i]*kc.y;
                s[i][2] += qv[i]*kc.z;
                s[i][3] += qv[i]*kc.w;
            }
        }

        // scale + mask (int32) + store to Ps[r][c]
        #pragma unroll
        for (int i = 0; i < 8; i++) {
            int r = tq*8 + i;
            const int* mp = mask + mrow_base + (size_t)r*Kn + kt + tk*4;
            int4 mm = *(const int4*)mp;
            float4 sv;
            sv.x = mm.x ? s[i][0]*0.125f : -1e30f;
            sv.y = mm.y ? s[i][1]*0.125f : -1e30f;
            sv.z = mm.z ? s[i][2]*0.125f : -1e30f;
            sv.w = mm.w ? s[i][3]*0.125f : -1e30f;
            *(float4*)&Ps[r*PS_STRIDE + tk*4] = sv;
        }
        __syncthreads();

        // Online softmax over this tile (one thread per row)
        if (tid < 128) {
            int r = tid;
            float mold = rowm[r];
            float mx = mold;
            #pragma unroll
            for (int c = 0; c < 64; c += 4) {
                float4 sv = *(float4*)&Ps[r*PS_STRIDE + c];
                mx = fmaxf(mx, fmaxf(fmaxf(sv.x, sv.y), fmaxf(sv.z, sv.w)));
            }
            float alpha = __expf(mold - mx);
            float sum = 0.f;
            #pragma unroll
            for (int c = 0; c < 64; c += 4) {
                float4 sv = *(float4*)&Ps[r*PS_STRIDE + c];
                sv.x = __expf(sv.x - mx);
                sv.y = __expf(sv.y - mx);
                sv.z = __expf(sv.z - mx);
                sv.w = __expf(sv.w - mx);
                sum += sv.x + sv.y + sv.z + sv.w;
                *(float4*)&Ps[r*PS_STRIDE + c] = sv;
            }
            rowm[r] = mx;
            rowl[r] = rowl[r]*alpha + sum;
            rowa[r] = alpha;
        }
        __syncthreads();

        // Rescale O and accumulate P·V
        float al[8];
        #pragma unroll
        for (int i = 0; i < 8; i++) al[i] = rowa[tq*8 + i];
        #pragma unroll
        for (int i = 0; i < 8; i++) {
            o[i][0] *= al[i]; o[i][1] *= al[i];
            o[i][2] *= al[i]; o[i][3] *= al[i];
        }

        #pragma unroll 4
        for (int k4 = 0; k4 < 64; k4 += 4) {
            float4 vv0 = *(float4*)&Vs[(k4+0)*KS_STRIDE + tk*4];
            float4 vv1 = *(float4*)&Vs[(k4+1)*KS_STRIDE + tk*4];
            float4 vv2 = *(float4*)&Vs[(k4+2)*KS_STRIDE + tk*4];
            float4 vv3 = *(float4*)&Vs[(k4+3)*KS_STRIDE + tk*4];
            #pragma unroll
            for (int i = 0; i < 8; i++) {
                float4 p = *(float4*)&Ps[(tq*8+i)*PS_STRIDE + k4];
                o[i][0] += p.x*vv0.x + p.y*vv1.x + p.z*vv2.x + p.w*vv3.x;
                o[i][1] += p.x*vv0.y + p.y*vv1.y + p.z*vv2.y + p.w*vv3.y;
                o[i][2] += p.x*vv0.z + p.y*vv1.z + p.z*vv2.z + p.w*vv3.z;
                o[i][3] += p.x*vv0.w + p.y*vv1.w + p.z*vv2.w + p.w*vv3.w;
            }
        }
        __syncthreads();
    }

    // Finalize: divide by l and store to (b, q, h*64+d)
    #pragma unroll
    for (int i = 0; i < 8; i++) {
        int r = q0 + tq*8 + i;
        float inv = 1.f / fmaxf(rowl[tq*8 + i], 1e-9f);
        float4 ov;
        ov.x = o[i][0]*inv; ov.y = o[i][1]*inv;
        ov.z = o[i][2]*inv; ov.w = o[i][3]*inv;
        *(float4*)&g_o[((size_t)(b*Qn + r))*(Hn*DHn) + h*DHn + tk*4] = ov;
    }
}

// ---------------------------------------------------------------------------
extern "C" void kernel_launch(void* const* d_in, const int* in_sizes, int n_in,
                              void* d_out, int out_size)
{
    const float* x    = (const float*)d_in[0];
    const int*   mask = (const int*)d_in[1];   // JAX bool -> int32 in harness
    const float* Wq   = (const float*)d_in[2];
    const float* Wk   = (const float*)d_in[3];
    const float* Wv   = (const float*)d_in[4];
    const float* Wo   = (const float*)d_in[5];
    const float* bo   = (const float*)d_in[6];
    float*       out  = (float*)d_out;

    qkv_gemm<<<dim3(24, 64), 256>>>(x, Wq, Wk, Wv);

    cudaFuncSetAttribute(attn_kernel,
                         cudaFuncAttributeMaxDynamicSharedMemorySize,
                         ATTN_SMEM_BYTES);
    attn_kernel<<<dim3(16, 64), 256, ATTN_SMEM_BYTES>>>(mask);

    out_gemm<<<dim3(8, 64), 256>>>(Wo, bo, out);
}

// round 4
// speedup vs baseline: 1.3771x; 1.3771x over previous
#include <cuda_runtime.h>
#include <cuda_bf16.h>
#include <cstdint>

#define Bn  4
#define Qn  2048
#define Kn  2048
#define Dn  1024
#define Hn  16
#define DHn 64
#define BHn (Bn*Hn)

// ---------------------------------------------------------------------------
// Scratch (__device__ globals; cudaMalloc is forbidden)
// ---------------------------------------------------------------------------
__device__ float g_q[(size_t)BHn*Qn*DHn];   // (b*H+h, q, d)
__device__ float g_k[(size_t)BHn*Kn*DHn];
__device__ float g_v[(size_t)BHn*Kn*DHn];
__device__ float g_o[(size_t)Bn*Qn*Hn*DHn]; // (b, q, h*64+d)

// split-bf16 copies
__device__ __nv_bfloat16 g_xhi[(size_t)8192*1024];
__device__ __nv_bfloat16 g_xlo[(size_t)8192*1024];
__device__ __nv_bfloat16 g_ohi[(size_t)8192*1024];
__device__ __nv_bfloat16 g_olo[(size_t)8192*1024];
__device__ __nv_bfloat16 g_wt_hi[(size_t)3072*1024];  // W_{q,k,v}^T  [n][k]
__device__ __nv_bfloat16 g_wt_lo[(size_t)3072*1024];
__device__ __nv_bfloat16 g_wot_hi[(size_t)1024*1024]; // Wo^T [n][k]
__device__ __nv_bfloat16 g_wot_lo[(size_t)1024*1024];

// ---------------------------------------------------------------------------
// helpers
// ---------------------------------------------------------------------------
__device__ __forceinline__ uint32_t smem_u32(const void* p) {
    uint32_t a;
    asm("{ .reg .u64 t; cvta.to.shared.u64 t, %1; cvt.u32.u64 %0, t; }"
        : "=r"(a) : "l"(p));
    return a;
}

#define SMEM_SWIZZLE_128B(byte_offset) \
    ((byte_offset) ^ (((byte_offset) >> 3) & 0x70))

__device__ __forceinline__ void ldmx4(uint32_t* r, uint32_t addr) {
    asm volatile("ldmatrix.sync.aligned.m8n8.x4.shared.b16 {%0,%1,%2,%3}, [%4];"
                 : "=r"(r[0]), "=r"(r[1]), "=r"(r[2]), "=r"(r[3]) : "r"(addr));
}

__device__ __forceinline__ void mma16816(float* c, const uint32_t* a,
                                         uint32_t b0, uint32_t b1) {
    asm volatile(
        "mma.sync.aligned.m16n8k16.row.col.f32.bf16.bf16.f32 "
        "{%0,%1,%2,%3}, {%4,%5,%6,%7}, {%8,%9}, {%0,%1,%2,%3};"
        : "+f"(c[0]), "+f"(c[1]), "+f"(c[2]), "+f"(c[3])
        : "r"(a[0]), "r"(a[1]), "r"(a[2]), "r"(a[3]), "r"(b0), "r"(b1));
}

// Load a 128-row x 64-bf16 tile (128 B/row) from gmem into SW128-swizzled smem
__device__ __forceinline__ void load_tile_bf16(uint32_t s_dst,
                                               const __nv_bfloat16* g,
                                               int tid) {
    #pragma unroll
    for (int i = 0; i < 4; i++) {
        int f = tid + 256*i;           // 0..1023
        int row = f >> 3;              // 0..127
        int c16 = f & 7;               // 16B chunk within row
        uint4 v = *(const uint4*)(g + (size_t)row*1024 + c16*8);
        uint32_t off = SMEM_SWIZZLE_128B((uint32_t)(row*128 + c16*16));
        asm volatile("st.shared.v4.b32 [%0], {%1,%2,%3,%4};"
                     :: "r"(s_dst + off), "r"(v.x), "r"(v.y), "r"(v.z), "r"(v.w));
    }
}

// ---------------------------------------------------------------------------
// Split-convert kernels: fp32 -> (bf16 hi, bf16 lo)
// ---------------------------------------------------------------------------
__device__ __forceinline__ void split4(float4 v, __nv_bfloat16* hi,
                                       __nv_bfloat16* lo, size_t idx) {
    float a[4] = {v.x, v.y, v.z, v.w};
    __nv_bfloat16 h[4], l[4];
    #pragma unroll
    for (int i = 0; i < 4; i++) {
        h[i] = __float2bfloat16(a[i]);
        l[i] = __float2bfloat16(a[i] - __bfloat162float(h[i]));
    }
    *(uint2*)(hi + idx) = *(uint2*)h;
    *(uint2*)(lo + idx) = *(uint2*)l;
}

__global__ void conv_split_x(const float* __restrict__ src) {
    size_t idx = ((size_t)blockIdx.x * 256 + threadIdx.x) * 4;
    split4(*(const float4*)(src + idx), g_xhi, g_xlo, idx);
}
__global__ void conv_split_o() {
    size_t idx = ((size_t)blockIdx.x * 256 + threadIdx.x) * 4;
    split4(*(const float4*)(g_o + idx), g_ohi, g_olo, idx);
}

// Transpose + split weights: W[k][n] (1024x1024) -> Wt[n][k] bf16 hi/lo
__global__ void conv_w(const float* __restrict__ Wq, const float* __restrict__ Wk,
                       const float* __restrict__ Wv, const float* __restrict__ Wo) {
    __shared__ float T[32][33];
    const float* src;
    __nv_bfloat16 *dh, *dl;
    int z = blockIdx.z;
    if      (z == 0) { src = Wq; dh = g_wt_hi;              dl = g_wt_lo; }
    else if (z == 1) { src = Wk; dh = g_wt_hi + 1024*1024;  dl = g_wt_lo + 1024*1024; }
    else if (z == 2) { src = Wv; dh = g_wt_hi + 2048*1024;  dl = g_wt_lo + 2048*1024; }
    else             { src = Wo; dh = g_wot_hi;             dl = g_wot_lo; }

    int n0 = blockIdx.x * 32, k0 = blockIdx.y * 32;
    int tx = threadIdx.x & 31, ty = threadIdx.x >> 5;   // 32 x 8
    #pragma unroll
    for (int i = 0; i < 4; i++)
        T[ty + 8*i][tx] = src[(size_t)(k0 + ty + 8*i) * 1024 + n0 + tx];
    __syncthreads();
    #pragma unroll
    for (int i = 0; i < 4; i++) {
        int n = n0 + ty + 8*i, k = k0 + tx;
        float v = T[tx][ty + 8*i];
        __nv_bfloat16 h = __float2bfloat16(v);
        dh[(size_t)n*1024 + k] = h;
        dl[(size_t)n*1024 + k] = __float2bfloat16(v - __bfloat162float(h));
    }
}

// ---------------------------------------------------------------------------
// mma.sync split-bf16 GEMM: 128x128 CTA tile, 8 warps (2m x 4n), warp 64x32
// ---------------------------------------------------------------------------
#define GEMM_SMEM_BYTES (4*16384)

struct GemmAcc { float a[4][4][4]; };   // [mi][ni][frag]

__device__ __forceinline__ void gemm_mainloop_mma(uint32_t sb, GemmAcc& A,
                                                  const __nv_bfloat16* Ahi,
                                                  const __nv_bfloat16* Alo,
                                                  const __nv_bfloat16* Bhi,
                                                  const __nv_bfloat16* Blo,
                                                  int tid) {
    const uint32_t sAh = sb;
    const uint32_t sAl = sAh + 16384;
    const uint32_t sBh = sAl + 16384;
    const uint32_t sBl = sBh + 16384;

    const int wid  = tid >> 5, lane = tid & 31;
    const int mw   = wid & 1, nw = wid >> 1;
    const uint32_t lrow  = lane & 15;          // ldmatrix row within 16
    const uint32_t lkoff = (lane >> 4) * 16;   // byte offset of k-half

    #pragma unroll
    for (int mi = 0; mi < 4; mi++)
        #pragma unroll
        for (int ni = 0; ni < 4; ni++)
            #pragma unroll
            for (int j = 0; j < 4; j++) A.a[mi][ni][j] = 0.f;

    for (int st = 0; st < 16; st++) {
        int k0 = st * 64;
        load_tile_bf16(sAh, Ahi + k0, tid);
        load_tile_bf16(sAl, Alo + k0, tid);
        load_tile_bf16(sBh, Bhi + k0, tid);
        load_tile_bf16(sBl, Blo + k0, tid);
        __syncthreads();

        #pragma unroll
        for (int ks = 0; ks < 4; ks++) {
            const uint32_t kb = ks*32 + lkoff;    // byte col within 128B row

            uint32_t ah[4][4];
            #pragma unroll
            for (int mi = 0; mi < 4; mi++)
                ldmx4(ah[mi], sAh + SMEM_SWIZZLE_128B(
                      (uint32_t)((mw*64 + mi*16 + lrow)*128) + kb));
            uint32_t bh[2][4];
            #pragma unroll
            for (int np = 0; np < 2; np++)
                ldmx4(bh[np], sBh + SMEM_SWIZZLE_128B(
                      (uint32_t)((nw*32 + np*16 + lrow)*128) + kb));

            // hi * hi
            #pragma unroll
            for (int mi = 0; mi < 4; mi++)
                #pragma unroll
                for (int ni = 0; ni < 4; ni++) {
                    int np = ni >> 1, s = ni & 1;
                    mma16816(A.a[mi][ni], ah[mi], bh[np][s], bh[np][s+2]);
                }

            // hi * lo
            uint32_t bl[2][4];
            #pragma unroll
            for (int np = 0; np < 2; np++)
                ldmx4(bl[np], sBl + SMEM_SWIZZLE_128B(
                      (uint32_t)((nw*32 + np*16 + lrow)*128) + kb));
            #pragma unroll
            for (int mi = 0; mi < 4; mi++)
                #pragma unroll
                for (int ni = 0; ni < 4; ni++) {
                    int np = ni >> 1, s = ni & 1;
                    mma16816(A.a[mi][ni], ah[mi], bl[np][s], bl[np][s+2]);
                }

            // lo * hi
            uint32_t al[4][4];
            #pragma unroll
            for (int mi = 0; mi < 4; mi++)
                ldmx4(al[mi], sAl + SMEM_SWIZZLE_128B(
                      (uint32_t)((mw*64 + mi*16 + lrow)*128) + kb));
            #pragma unroll
            for (int mi = 0; mi < 4; mi++)
                #pragma unroll
                for (int ni = 0; ni < 4; ni++) {
                    int np = ni >> 1, s = ni & 1;
                    mma16816(A.a[mi][ni], al[mi], bh[np][s], bh[np][s+2]);
                }
        }
        __syncthreads();
    }
}

__global__ __launch_bounds__(256)
void qkv_gemm_mma() {
    extern __shared__ char smem[];
    uint32_t sb = smem_u32(smem);
    int tid = threadIdx.x, lane = tid & 31, wid = tid >> 5;
    int mw = wid & 1, nw = wid >> 1;
    int n_base = blockIdx.x * 128;     // over 3072
    int m0 = blockIdx.y * 128;

    float* dst;
    if      (n_base < 1024) dst = g_q;
    else if (n_base < 2048) dst = g_k;
    else                    dst = g_v;
    int col_base = n_base & 1023;

    GemmAcc acc;
    gemm_mainloop_mma(sb, acc,
                      g_xhi + (size_t)m0*1024, g_xlo + (size_t)m0*1024,
                      g_wt_hi + (size_t)n_base*1024, g_wt_lo + (size_t)n_base*1024,
                      tid);

    int g = lane >> 2, tg = lane & 3;
    #pragma unroll
    for (int mi = 0; mi < 4; mi++) {
        #pragma unroll
        for (int ni = 0; ni < 4; ni++) {
            int col = col_base + nw*32 + ni*8 + tg*2;
            int h = col >> 6, d = col & 63;
            #pragma unroll
            for (int half = 0; half < 2; half++) {
                int m = m0 + mw*64 + mi*16 + g + half*8;
                int bb = m >> 11, qp = m & 2047;
                float2 v = make_float2(acc.a[mi][ni][half*2],
                                       acc.a[mi][ni][half*2+1]);
                *(float2*)&dst[(((size_t)(bb*Hn + h))*Qn + qp)*DHn + d] = v;
            }
        }
    }
}

__global__ __launch_bounds__(256)
void out_gemm_mma(const float* __restrict__ bo, float* __restrict__ out) {
    extern __shared__ char smem[];
    uint32_t sb = smem_u32(smem);
    int tid = threadIdx.x, lane = tid & 31, wid = tid >> 5;
    int mw = wid & 1, nw = wid >> 1;
    int n_base = blockIdx.x * 128;     // over 1024
    int m0 = blockIdx.y * 128;

    GemmAcc acc;
    gemm_mainloop_mma(sb, acc,
                      g_ohi + (size_t)m0*1024, g_olo + (size_t)m0*1024,
                      g_wot_hi + (size_t)n_base*1024, g_wot_lo + (size_t)n_base*1024,
                      tid);

    int g = lane >> 2, tg = lane & 3;
    #pragma unroll
    for (int ni = 0; ni < 4; ni++) {
        int n = n_base + nw*32 + ni*8 + tg*2;
        float2 bias = *(const float2*)&bo[n];
        #pragma unroll
        for (int mi = 0; mi < 4; mi++) {
            #pragma unroll
            for (int half = 0; half < 2; half++) {
                int m = m0 + mw*64 + mi*16 + g + half*8;
                float2 v = make_float2(acc.a[mi][ni][half*2] + bias.x,
                                       acc.a[mi][ni][half*2+1] + bias.y);
                *(float2*)&out[(size_t)m*1024 + n] = v;
            }
        }
    }
}

// ---------------------------------------------------------------------------
// Flash attention, fp32 (unchanged from passing R2 kernel)
// ---------------------------------------------------------------------------
#define AQ 128
#define AK 64
#define QS_STRIDE 132
#define KS_STRIDE 68
#define PS_STRIDE 68
#define ATTN_SMEM_FLOATS (64*QS_STRIDE + 64*KS_STRIDE + 64*KS_STRIDE + 128*PS_STRIDE + 384)
#define ATTN_SMEM_BYTES (ATTN_SMEM_FLOATS * 4)

__global__ __launch_bounds__(256, 2)
void attn_kernel(const int* __restrict__ mask)
{
    extern __shared__ float sm[];
    float* Qs   = sm;
    float* Ks   = Qs + 64*QS_STRIDE;
    float* Vs   = Ks + 64*KS_STRIDE;
    float* Ps   = Vs + 64*KS_STRIDE;
    float* rowm = Ps + 128*PS_STRIDE;
    float* rowl = rowm + 128;
    float* rowa = rowl + 128;

    const int tid = threadIdx.x;
    const int bh  = blockIdx.y;
    const int qt  = blockIdx.x;
    const int b   = bh >> 4;
    const int h   = bh & 15;
    const int q0  = qt * AQ;

    const float* qptr = g_q + (size_t)bh*Qn*DHn + (size_t)q0*DHn;
    const float* kptr = g_k + (size_t)bh*Kn*DHn;
    const float* vptr = g_v + (size_t)bh*Kn*DHn;

    for (int f = tid; f < AQ*16; f += 256) {
        int r  = f >> 4;
        int d4 = (f & 15) << 2;
        float4 v = *(const float4*)&qptr[(size_t)r*DHn + d4];
        Qs[(d4+0)*QS_STRIDE + r] = v.x;
        Qs[(d4+1)*QS_STRIDE + r] = v.y;
        Qs[(d4+2)*QS_STRIDE + r] = v.z;
        Qs[(d4+3)*QS_STRIDE + r] = v.w;
    }
    if (tid < 128) { rowm[tid] = -1e30f; rowl[tid] = 0.f; }
    __syncthreads();

    const int tq = tid >> 4;
    const int tk = tid & 15;

    float o[8][4];
    #pragma unroll
    for (int i = 0; i < 8; i++)
        #pragma unroll
        for (int j = 0; j < 4; j++) o[i][j] = 0.f;

    const size_t mrow_base = ((size_t)b*Qn + q0) * Kn;

    for (int kt = 0; kt < Kn; kt += AK) {
        for (int f = tid; f < AK*16; f += 256) {
            int r  = f >> 4;
            int d4 = (f & 15) << 2;
            float4 kv = *(const float4*)&kptr[(size_t)(kt + r)*DHn + d4];
            Ks[(d4+0)*KS_STRIDE + r] = kv.x;
            Ks[(d4+1)*KS_STRIDE + r] = kv.y;
            Ks[(d4+2)*KS_STRIDE + r] = kv.z;
            Ks[(d4+3)*KS_STRIDE + r] = kv.w;
            float4 vv = *(const float4*)&vptr[(size_t)(kt + r)*DHn + d4];
            *(float4*)&Vs[r*KS_STRIDE + d4] = vv;
        }
        __syncthreads();

        float s[8][4];
        #pragma unroll
        for (int i = 0; i < 8; i++)
            #pragma unroll
            for (int j = 0; j < 4; j++) s[i][j] = 0.f;

        #pragma unroll 8
        for (int d = 0; d < 64; d++) {
            float4 qa = *(const float4*)&Qs[d*QS_STRIDE + tq*8];
            float4 qb = *(const float4*)&Qs[d*QS_STRIDE + tq*8 + 4];
            float4 kc = *(const float4*)&Ks[d*KS_STRIDE + tk*4];
            float qv[8] = {qa.x,qa.y,qa.z,qa.w,qb.x,qb.y,qb.z,qb.w};
            #pragma unroll
            for (int i = 0; i < 8; i++) {
                s[i][0] += qv[i]*kc.x;
                s[i][1] += qv[i]*kc.y;
                s[i][2] += qv[i]*kc.z;
                s[i][3] += qv[i]*kc.w;
            }
        }

        #pragma unroll
        for (int i = 0; i < 8; i++) {
            int r = tq*8 + i;
            const int* mp = mask + mrow_base + (size_t)r*Kn + kt + tk*4;
            int4 mm = *(const int4*)mp;
            float4 sv;
            sv.x = mm.x ? s[i][0]*0.125f : -1e30f;
            sv.y = mm.y ? s[i][1]*0.125f : -1e30f;
            sv.z = mm.z ? s[i][2]*0.125f : -1e30f;
            sv.w = mm.w ? s[i][3]*0.125f : -1e30f;
            *(float4*)&Ps[r*PS_STRIDE + tk*4] = sv;
        }
        __syncthreads();

        if (tid < 128) {
            int r = tid;
            float mold = rowm[r];
            float mx = mold;
            #pragma unroll
            for (int c = 0; c < 64; c += 4) {
                float4 sv = *(float4*)&Ps[r*PS_STRIDE + c];
                mx = fmaxf(mx, fmaxf(fmaxf(sv.x, sv.y), fmaxf(sv.z, sv.w)));
            }
            float alpha = __expf(mold - mx);
            float sum = 0.f;
            #pragma unroll
            for (int c = 0; c < 64; c += 4) {
                float4 sv = *(float4*)&Ps[r*PS_STRIDE + c];
                sv.x = __expf(sv.x - mx);
                sv.y = __expf(sv.y - mx);
                sv.z = __expf(sv.z - mx);
                sv.w = __expf(sv.w - mx);
                sum += sv.x + sv.y + sv.z + sv.w;
                *(float4*)&Ps[r*PS_STRIDE + c] = sv;
            }
            rowm[r] = mx;
            rowl[r] = rowl[r]*alpha + sum;
            rowa[r] = alpha;
        }
        __syncthreads();

        float al[8];
        #pragma unroll
        for (int i = 0; i < 8; i++) al[i] = rowa[tq*8 + i];
        #pragma unroll
        for (int i = 0; i < 8; i++) {
            o[i][0] *= al[i]; o[i][1] *= al[i];
            o[i][2] *= al[i]; o[i][3] *= al[i];
        }

        #pragma unroll 4
        for (int k4 = 0; k4 < 64; k4 += 4) {
            float4 vv0 = *(float4*)&Vs[(k4+0)*KS_STRIDE + tk*4];
            float4 vv1 = *(float4*)&Vs[(k4+1)*KS_STRIDE + tk*4];
            float4 vv2 = *(float4*)&Vs[(k4+2)*KS_STRIDE + tk*4];
            float4 vv3 = *(float4*)&Vs[(k4+3)*KS_STRIDE + tk*4];
            #pragma unroll
            for (int i = 0; i < 8; i++) {
                float4 p = *(float4*)&Ps[(tq*8+i)*PS_STRIDE + k4];
                o[i][0] += p.x*vv0.x + p.y*vv1.x + p.z*vv2.x + p.w*vv3.x;
                o[i][1] += p.x*vv0.y + p.y*vv1.y + p.z*vv2.y + p.w*vv3.y;
                o[i][2] += p.x*vv0.z + p.y*vv1.z + p.z*vv2.z + p.w*vv3.z;
                o[i][3] += p.x*vv0.w + p.y*vv1.w + p.z*vv2.w + p.w*vv3.w;
            }
        }
        __syncthreads();
    }

    #pragma unroll
    for (int i = 0; i < 8; i++) {
        int r = q0 + tq*8 + i;
        float inv = 1.f / fmaxf(rowl[tq*8 + i], 1e-9f);
        float4 ov;
        ov.x = o[i][0]*inv; ov.y = o[i][1]*inv;
        ov.z = o[i][2]*inv; ov.w = o[i][3]*inv;
        *(float4*)&g_o[((size_t)(b*Qn + r))*(Hn*DHn) + h*DHn + tk*4] = ov;
    }
}

// ---------------------------------------------------------------------------
extern "C" void kernel_launch(void* const* d_in, const int* in_sizes, int n_in,
                              void* d_out, int out_size)
{
    const float* x    = (const float*)d_in[0];
    const int*   mask = (const int*)d_in[1];
    const float* Wq   = (const float*)d_in[2];
    const float* Wk   = (const float*)d_in[3];
    const float* Wv   = (const float*)d_in[4];
    const float* Wo   = (const float*)d_in[5];
    const float* bo   = (const float*)d_in[6];
    float*       out  = (float*)d_out;

    cudaFuncSetAttribute(qkv_gemm_mma,
                         cudaFuncAttributeMaxDynamicSharedMemorySize, GEMM_SMEM_BYTES);
    cudaFuncSetAttribute(out_gemm_mma,
                         cudaFuncAttributeMaxDynamicSharedMemorySize, GEMM_SMEM_BYTES);
    cudaFuncSetAttribute(attn_kernel,
                         cudaFuncAttributeMaxDynamicSharedMemorySize, ATTN_SMEM_BYTES);

    // 1. split-convert x; transpose+split weights
    conv_split_x<<<8192, 256>>>(x);
    conv_w<<<dim3(32, 32, 4), 256>>>(Wq, Wk, Wv, Wo);

    // 2. QKV projection (mma.sync split-bf16)
    qkv_gemm_mma<<<dim3(24, 64), 256, GEMM_SMEM_BYTES>>>();

    // 3. attention (fp32)
    attn_kernel<<<dim3(16, 64), 256, ATTN_SMEM_BYTES>>>(mask);

    // 4. split-convert attention output; output projection + bias
    conv_split_o<<<8192, 256>>>();
    out_gemm_mma<<<dim3(8, 64), 256, GEMM_SMEM_BYTES>>>(bo, out);
}

// round 6
// speedup vs baseline: 2.3228x; 1.6867x over previous
#include <cuda_runtime.h>
#include <cuda_bf16.h>
#include <cuda_fp16.h>
#include <cstdint>

#define Bn  4
#define Qn  2048
#define Kn  2048
#define Dn  1024
#define Hn  16
#define DHn 64
#define BHn (Bn*Hn)

// ---------------------------------------------------------------------------
// Scratch (__device__ globals; cudaMalloc is forbidden)
// ---------------------------------------------------------------------------
__device__ float g_o[(size_t)Bn*Qn*Hn*DHn];          // attention out (b, q, h*64+d)

// fp16 split Q/K, fp16 V  (written by qkv epilogue), layout (b*H+h, seq, 64)
__device__ __half g_qhi[(size_t)BHn*Qn*DHn];
__device__ __half g_qlo[(size_t)BHn*Qn*DHn];
__device__ __half g_khi[(size_t)BHn*Kn*DHn];
__device__ __half g_klo[(size_t)BHn*Kn*DHn];
__device__ __half g_vh [(size_t)BHn*Kn*DHn];

// packed mask bits: [b][q][64 words]
__device__ uint32_t g_mbits[(size_t)Bn*Qn*64];

// split-bf16 GEMM operands
__device__ __nv_bfloat16 g_xhi[(size_t)8192*1024];
__device__ __nv_bfloat16 g_xlo[(size_t)8192*1024];
__device__ __nv_bfloat16 g_ohi[(size_t)8192*1024];
__device__ __nv_bfloat16 g_olo[(size_t)8192*1024];
__device__ __nv_bfloat16 g_wt_hi[(size_t)3072*1024];  // W_{q,k,v}^T  [n][k]
__device__ __nv_bfloat16 g_wt_lo[(size_t)3072*1024];
__device__ __nv_bfloat16 g_wot_hi[(size_t)1024*1024]; // Wo^T [n][k]
__device__ __nv_bfloat16 g_wot_lo[(size_t)1024*1024];

// ---------------------------------------------------------------------------
// helpers
// ---------------------------------------------------------------------------
__device__ __forceinline__ uint32_t smem_u32(const void* p) {
    uint32_t a;
    asm("{ .reg .u64 t; cvta.to.shared.u64 t, %1; cvt.u32.u64 %0, t; }"
        : "=r"(a) : "l"(p));
    return a;
}

__device__ __forceinline__ uint32_t h2_as_u32(__half2 v) {
    return *reinterpret_cast<uint32_t*>(&v);
}

#define SMEM_SWIZZLE_128B(byte_offset) \
    ((byte_offset) ^ (((byte_offset) >> 3) & 0x70))

__device__ __forceinline__ void ldmx4(uint32_t* r, uint32_t addr) {
    asm volatile("ldmatrix.sync.aligned.m8n8.x4.shared.b16 {%0,%1,%2,%3}, [%4];"
                 : "=r"(r[0]), "=r"(r[1]), "=r"(r[2]), "=r"(r[3]) : "r"(addr));
}
__device__ __forceinline__ void ldmx4t(uint32_t* r, uint32_t addr) {
    asm volatile("ldmatrix.sync.aligned.m8n8.x4.trans.shared.b16 {%0,%1,%2,%3}, [%4];"
                 : "=r"(r[0]), "=r"(r[1]), "=r"(r[2]), "=r"(r[3]) : "r"(addr));
}

__device__ __forceinline__ void mma16816(float* c, const uint32_t* a,
                                         uint32_t b0, uint32_t b1) {
    asm volatile(
        "mma.sync.aligned.m16n8k16.row.col.f32.bf16.bf16.f32 "
        "{%0,%1,%2,%3}, {%4,%5,%6,%7}, {%8,%9}, {%0,%1,%2,%3};"
        : "+f"(c[0]), "+f"(c[1]), "+f"(c[2]), "+f"(c[3])
        : "r"(a[0]), "r"(a[1]), "r"(a[2]), "r"(a[3]), "r"(b0), "r"(b1));
}
__device__ __forceinline__ void mma16816h(float* c, const uint32_t* a,
                                          uint32_t b0, uint32_t b1) {
    asm volatile(
        "mma.sync.aligned.m16n8k16.row.col.f32.f16.f16.f32 "
        "{%0,%1,%2,%3}, {%4,%5,%6,%7}, {%8,%9}, {%0,%1,%2,%3};"
        : "+f"(c[0]), "+f"(c[1]), "+f"(c[2]), "+f"(c[3])
        : "r"(a[0]), "r"(a[1]), "r"(a[2]), "r"(a[3]), "r"(b0), "r"(b1));
}

// fast exp2 (FFMA-only, rel err ~2.4e-6): deg-5 Taylor on [-0.5, 0.5]
__device__ __forceinline__ float fexp2(float t) {
    t = fmaxf(t, -80.f);
    int i = __float2int_rn(t);
    float f = t - (float)i;
    float p = 1.3333558146e-3f;
    p = fmaf(p, f, 9.6181291057e-3f);
    p = fmaf(p, f, 5.5504108664e-2f);
    p = fmaf(p, f, 2.4022650696e-1f);
    p = fmaf(p, f, 6.9314718056e-1f);
    p = fmaf(p, f, 1.0f);
    return p * __int_as_float((i + 127) << 23);
}
#define LOG2E 1.4426950408889634f

// Load a 128-row x 64-elem (bf16/half) tile (128 B/row) into SW128 smem
__device__ __forceinline__ void load_tile_bf16(uint32_t s_dst,
                                               const __nv_bfloat16* g,
                                               int tid) {
    #pragma unroll
    for (int i = 0; i < 4; i++) {
        int f = tid + 256*i;
        int row = f >> 3;
        int c16 = f & 7;
        uint4 v = *(const uint4*)(g + (size_t)row*1024 + c16*8);
        uint32_t off = SMEM_SWIZZLE_128B((uint32_t)(row*128 + c16*16));
        asm volatile("st.shared.v4.b32 [%0], {%1,%2,%3,%4};"
                     :: "r"(s_dst + off), "r"(v.x), "r"(v.y), "r"(v.z), "r"(v.w));
    }
}
__device__ __forceinline__ void sts16(uint32_t addr, uint4 v) {
    asm volatile("st.shared.v4.b32 [%0], {%1,%2,%3,%4};"
                 :: "r"(addr), "r"(v.x), "r"(v.y), "r"(v.z), "r"(v.w));
}

// ---------------------------------------------------------------------------
// Split-convert kernels: fp32 -> (bf16 hi, bf16 lo)
// ---------------------------------------------------------------------------
__device__ __forceinline__ void split4(float4 v, __nv_bfloat16* hi,
                                       __nv_bfloat16* lo, size_t idx) {
    float a[4] = {v.x, v.y, v.z, v.w};
    __nv_bfloat16 h[4], l[4];
    #pragma unroll
    for (int i = 0; i < 4; i++) {
        h[i] = __float2bfloat16(a[i]);
        l[i] = __float2bfloat16(a[i] - __bfloat162float(h[i]));
    }
    *(uint2*)(hi + idx) = *(uint2*)h;
    *(uint2*)(lo + idx) = *(uint2*)l;
}

__global__ void conv_split_x(const float* __restrict__ src) {
    size_t idx = ((size_t)blockIdx.x * 256 + threadIdx.x) * 4;
    split4(*(const float4*)(src + idx), g_xhi, g_xlo, idx);
}
__global__ void conv_split_o() {
    size_t idx = ((size_t)blockIdx.x * 256 + threadIdx.x) * 4;
    split4(*(const float4*)(g_o + idx), g_ohi, g_olo, idx);
}

// Transpose + split weights: W[k][n] (1024x1024) -> Wt[n][k] bf16 hi/lo
__global__ void conv_w(const float* __restrict__ Wq, const float* __restrict__ Wk,
                       const float* __restrict__ Wv, const float* __restrict__ Wo) {
    __shared__ float T[32][33];
    const float* src;
    __nv_bfloat16 *dh, *dl;
    int z = blockIdx.z;
    if      (z == 0) { src = Wq; dh = g_wt_hi;              dl = g_wt_lo; }
    else if (z == 1) { src = Wk; dh = g_wt_hi + 1024*1024;  dl = g_wt_lo + 1024*1024; }
    else if (z == 2) { src = Wv; dh = g_wt_hi + 2048*1024;  dl = g_wt_lo + 2048*1024; }
    else             { src = Wo; dh = g_wot_hi;             dl = g_wot_lo; }

    int n0 = blockIdx.x * 32, k0 = blockIdx.y * 32;
    int tx = threadIdx.x & 31, ty = threadIdx.x >> 5;
    #pragma unroll
    for (int i = 0; i < 4; i++)
        T[ty + 8*i][tx] = src[(size_t)(k0 + ty + 8*i) * 1024 + n0 + tx];
    __syncthreads();
    #pragma unroll
    for (int i = 0; i < 4; i++) {
        int n = n0 + ty + 8*i, k = k0 + tx;
        float v = T[tx][ty + 8*i];
        __nv_bfloat16 h = __float2bfloat16(v);
        dh[(size_t)n*1024 + k] = h;
        dl[(size_t)n*1024 + k] = __float2bfloat16(v - __bfloat162float(h));
    }
}

// Pack int32 mask -> bitmask via ballot. One warp packs 32 words (1024 ints).
__global__ void pack_mask(const int* __restrict__ mask) {
    int warp = (blockIdx.x * blockDim.x + threadIdx.x) >> 5;
    int lane = threadIdx.x & 31;
    size_t base = (size_t)warp * 1024;
    #pragma unroll 4
    for (int r = 0; r < 32; r++) {
        int v = mask[base + r*32 + lane];
        unsigned bits = __ballot_sync(0xffffffffu, v != 0);
        if (lane == 0) g_mbits[(size_t)warp*32 + r] = bits;
    }
}

// ---------------------------------------------------------------------------
// mma.sync split-bf16 GEMM: 128x128 CTA tile, 8 warps (2m x 4n), warp 64x32
// ---------------------------------------------------------------------------
#define GEMM_SMEM_BYTES (4*16384)

struct GemmAcc { float a[4][4][4]; };

__device__ __forceinline__ void gemm_mainloop_mma(uint32_t sb, GemmAcc& A,
                                                  const __nv_bfloat16* Ahi,
                                                  const __nv_bfloat16* Alo,
                                                  const __nv_bfloat16* Bhi,
                                                  const __nv_bfloat16* Blo,
                                                  int tid) {
    const uint32_t sAh = sb;
    const uint32_t sAl = sAh + 16384;
    const uint32_t sBh = sAl + 16384;
    const uint32_t sBl = sBh + 16384;

    const int wid  = tid >> 5, lane = tid & 31;
    const int mw   = wid & 1, nw = wid >> 1;
    const uint32_t lrow  = lane & 15;
    const uint32_t lkoff = (lane >> 4) * 16;

    #pragma unroll
    for (int mi = 0; mi < 4; mi++)
        #pragma unroll
        for (int ni = 0; ni < 4; ni++)
            #pragma unroll
            for (int j = 0; j < 4; j++) A.a[mi][ni][j] = 0.f;

    for (int st = 0; st < 16; st++) {
        int k0 = st * 64;
        load_tile_bf16(sAh, Ahi + k0, tid);
        load_tile_bf16(sAl, Alo + k0, tid);
        load_tile_bf16(sBh, Bhi + k0, tid);
        load_tile_bf16(sBl, Blo + k0, tid);
        __syncthreads();

        #pragma unroll
        for (int ks = 0; ks < 4; ks++) {
            const uint32_t kb = ks*32 + lkoff;

            uint32_t ah[4][4];
            #pragma unroll
            for (int mi = 0; mi < 4; mi++)
                ldmx4(ah[mi], sAh + SMEM_SWIZZLE_128B(
                      (uint32_t)((mw*64 + mi*16 + lrow)*128) + kb));
            uint32_t bh[2][4];
            #pragma unroll
            for (int np = 0; np < 2; np++)
                ldmx4(bh[np], sBh + SMEM_SWIZZLE_128B(
                      (uint32_t)((nw*32 + np*16 + lrow)*128) + kb));

            #pragma unroll
            for (int mi = 0; mi < 4; mi++)
                #pragma unroll
                for (int ni = 0; ni < 4; ni++) {
                    int np = ni >> 1, s = ni & 1;
                    mma16816(A.a[mi][ni], ah[mi], bh[np][s], bh[np][s+2]);
                }

            uint32_t bl[2][4];
            #pragma unroll
            for (int np = 0; np < 2; np++)
                ldmx4(bl[np], sBl + SMEM_SWIZZLE_128B(
                      (uint32_t)((nw*32 + np*16 + lrow)*128) + kb));
            #pragma unroll
            for (int mi = 0; mi < 4; mi++)
                #pragma unroll
                for (int ni = 0; ni < 4; ni++) {
                    int np = ni >> 1, s = ni & 1;
                    mma16816(A.a[mi][ni], ah[mi], bl[np][s], bl[np][s+2]);
                }

            uint32_t al[4][4];
            #pragma unroll
            for (int mi = 0; mi < 4; mi++)
                ldmx4(al[mi], sAl + SMEM_SWIZZLE_128B(
                      (uint32_t)((mw*64 + mi*16 + lrow)*128) + kb));
            #pragma unroll
            for (int mi = 0; mi < 4; mi++)
                #pragma unroll
                for (int ni = 0; ni < 4; ni++) {
                    int np = ni >> 1, s = ni & 1;
                    mma16816(A.a[mi][ni], al[mi], bh[np][s], bh[np][s+2]);
                }
        }
        __syncthreads();
    }
}

__global__ __launch_bounds__(256)
void qkv_gemm_mma() {
    extern __shared__ char smem[];
    uint32_t sb = smem_u32(smem);
    int tid = threadIdx.x, lane = tid & 31, wid = tid >> 5;
    int mw = wid & 1, nw = wid >> 1;
    int n_base = blockIdx.x * 128;
    int m0 = blockIdx.y * 128;

    int kind;                      // 0=Q (hi/lo), 1=K (hi/lo), 2=V (fp16)
    if      (n_base < 1024) kind = 0;
    else if (n_base < 2048) kind = 1;
    else                    kind = 2;
    int col_base = n_base & 1023;

    GemmAcc acc;
    gemm_mainloop_mma(sb, acc,
                      g_xhi + (size_t)m0*1024, g_xlo + (size_t)m0*1024,
                      g_wt_hi + (size_t)n_base*1024, g_wt_lo + (size_t)n_base*1024,
                      tid);

    int g = lane >> 2, tg = lane & 3;
    #pragma unroll
    for (int mi = 0; mi < 4; mi++) {
        #pragma unroll
        for (int ni = 0; ni < 4; ni++) {
            int col = col_base + nw*32 + ni*8 + tg*2;
            int h = col >> 6, d = col & 63;
            #pragma unroll
            for (int half_ = 0; half_ < 2; half_++) {
                int m = m0 + mw*64 + mi*16 + g + half_*8;
                int bb = m >> 11, qp = m & 2047;
                float vx = acc.a[mi][ni][half_*2];
                float vy = acc.a[mi][ni][half_*2+1];
                size_t idx = (((size_t)(bb*Hn + h))*Qn + qp)*DHn + d;
                __half hx = __float2half_rn(vx), hy = __float2half_rn(vy);
                __half2 hh = __halves2half2(hx, hy);
                if (kind == 2) {
                    *(__half2*)&g_vh[idx] = hh;
                } else {
                    __half lx = __float2half_rn(vx - __half2float(hx));
                    __half ly = __float2half_rn(vy - __half2float(hy));
                    __half2 ll = __halves2half2(lx, ly);
                    if (kind == 0) {
                        *(__half2*)&g_qhi[idx] = hh;
                        *(__half2*)&g_qlo[idx] = ll;
                    } else {
                        *(__half2*)&g_khi[idx] = hh;
                        *(__half2*)&g_klo[idx] = ll;
                    }
                }
            }
        }
    }
}

__global__ __launch_bounds__(256)
void out_gemm_mma(const float* __restrict__ bo, float* __restrict__ out) {
    extern __shared__ char smem[];
    uint32_t sb = smem_u32(smem);
    int tid = threadIdx.x, lane = tid & 31, wid = tid >> 5;
    int mw = wid & 1, nw = wid >> 1;
    int n_base = blockIdx.x * 128;
    int m0 = blockIdx.y * 128;

    GemmAcc acc;
    gemm_mainloop_mma(sb, acc,
                      g_ohi + (size_t)m0*1024, g_olo + (size_t)m0*1024,
                      g_wot_hi + (size_t)n_base*1024, g_wot_lo + (size_t)n_base*1024,
                      tid);

    int g = lane >> 2, tg = lane & 3;
    #pragma unroll
    for (int ni = 0; ni < 4; ni++) {
        int n = n_base + nw*32 + ni*8 + tg*2;
        float2 bias = *(const float2*)&bo[n];
        #pragma unroll
        for (int mi = 0; mi < 4; mi++) {
            #pragma unroll
            for (int half_ = 0; half_ < 2; half_++) {
                int m = m0 + mw*64 + mi*16 + g + half_*8;
                float2 v = make_float2(acc.a[mi][ni][half_*2] + bias.x,
                                       acc.a[mi][ni][half_*2+1] + bias.y);
                *(float2*)&out[(size_t)m*1024 + n] = v;
            }
        }
    }
}

// ---------------------------------------------------------------------------
// Flash attention via mma.sync: CTA = 128 q-rows of one (b,h); 8 warps,
// warp owns 16 rows x full 64-key tile. Split-fp16 QK^T (3 products),
// fp16 P*V, register-resident P, FFMA softmax.
// ---------------------------------------------------------------------------
#define ATTN_SMEM_BYTES (16384*2 + 8192*3)   // Qhi,Qlo + Khi,Klo,Vh

__global__ __launch_bounds__(256)
void attn_mma() {
    extern __shared__ char smem[];
    uint32_t sb = smem_u32(smem);
    const uint32_t sQh = sb;
    const uint32_t sQl = sQh + 16384;
    const uint32_t sKh = sQl + 16384;
    const uint32_t sKl = sKh + 8192;
    const uint32_t sVh = sKl + 8192;

    const int tid = threadIdx.x;
    const int w = tid >> 5, lane = tid & 31;
    const int g = lane >> 2, tg = lane & 3;
    const uint32_t lrow = lane & 15;
    const uint32_t lkhalf = (lane >> 4) * 16;

    const int bh = blockIdx.y;
    const int b = bh >> 4, h = bh & 15;
    const int q0 = blockIdx.x * 128;

    const __half* qhp = g_qhi + ((size_t)bh*Qn + q0)*DHn;
    const __half* qlp = g_qlo + ((size_t)bh*Qn + q0)*DHn;
    const __half* khp = g_khi + (size_t)bh*Kn*DHn;
    const __half* klp = g_klo + (size_t)bh*Kn*DHn;
    const __half* vhp = g_vh  + (size_t)bh*Kn*DHn;

    // stage Q tiles (128 x 64 half = 16KB each)
    #pragma unroll
    for (int i = 0; i < 4; i++) {
        int f = tid + 256*i;
        int row = f >> 3, c16 = f & 7;
        uint32_t off = SMEM_SWIZZLE_128B((uint32_t)(row*128 + c16*16));
        sts16(sQh + off, *(const uint4*)(qhp + (size_t)row*DHn + c16*8));
        sts16(sQl + off, *(const uint4*)(qlp + (size_t)row*DHn + c16*8));
    }
    __syncthreads();

    // Q fragments (per warp rows w*16..w*16+15), 4 k-steps
    uint32_t qh[4][4], ql[4][4];
    #pragma unroll
    for (int ks = 0; ks < 4; ks++) {
        uint32_t kb = ks*32 + lkhalf;
        uint32_t roff = SMEM_SWIZZLE_128B((uint32_t)((w*16 + lrow)*128) + kb);
        ldmx4(qh[ks], sQh + roff);
        ldmx4(ql[ks], sQl + roff);
    }
    __syncthreads();

    float o[8][4];
    #pragma unroll
    for (int j = 0; j < 8; j++)
        #pragma unroll
        for (int c = 0; c < 4; c++) o[j][c] = 0.f;
    float mrun0 = -1e30f, mrun1 = -1e30f;
    float lrun0 = 0.f, lrun1 = 0.f;

    const int r0 = w*16 + g;            // local row for c0,c1
    const int r1 = r0 + 8;              // local row for c2,c3
    const uint32_t* mb0 = g_mbits + ((size_t)b*Qn + q0 + r0)*64;
    const uint32_t* mb1 = g_mbits + ((size_t)b*Qn + q0 + r1)*64;

    for (int kt = 0; kt < Kn; kt += 64) {
        // load K hi/lo + V tiles (64 x 64 half each)
        #pragma unroll
        for (int i = 0; i < 2; i++) {
            int f = tid + 256*i;
            int row = f >> 3, c16 = f & 7;
            uint32_t off = SMEM_SWIZZLE_128B((uint32_t)(row*128 + c16*16));
            size_t gidx = (size_t)(kt + row)*DHn + c16*8;
            sts16(sKh + off, *(const uint4*)(khp + gidx));
            sts16(sKl + off, *(const uint4*)(klp + gidx));
            sts16(sVh + off, *(const uint4*)(vhp + gidx));
        }
        __syncthreads();

        // S = Q K^T  (split-fp16, 3 products)
        float s[8][4];
        #pragma unroll
        for (int j = 0; j < 8; j++)
            #pragma unroll
            for (int c = 0; c < 4; c++) s[j][c] = 0.f;

        #pragma unroll
        for (int ks = 0; ks < 4; ks++) {
            uint32_t kb = ks*32 + lkhalf;
            #pragma unroll
            for (int kg = 0; kg < 4; kg++) {
                uint32_t roff = SMEM_SWIZZLE_128B(
                    (uint32_t)((kg*16 + lrow)*128) + kb);
                uint32_t bh_[4], bl_[4];
                ldmx4(bh_, sKh + roff);
                ldmx4(bl_, sKl + roff);
                #pragma unroll
                for (int s2 = 0; s2 < 2; s2++) {
                    int j = 2*kg + s2;
                    mma16816h(s[j], qh[ks], bh_[s2], bh_[s2+2]);
                    mma16816h(s[j], ql[ks], bh_[s2], bh_[s2+2]);
                    mma16816h(s[j], qh[ks], bl_[s2], bl_[s2+2]);
                }
            }
        }

        // mask + scale
        uint2 mw0 = *(const uint2*)(mb0 + (kt >> 5));
        uint2 mw1 = *(const uint2*)(mb1 + (kt >> 5));
        #pragma unroll
        for (int j = 0; j < 8; j++) {
            int c = j*8 + tg*2;
            uint32_t w0 = (c & 32) ? mw0.y : mw0.x;
            uint32_t w1 = (c & 32) ? mw1.y : mw1.x;
            int sh = c & 31;
            s[j][0] = ((w0 >> sh) & 1u)     ? s[j][0]*0.125f : -1e30f;
            s[j][1] = ((w0 >> (sh+1)) & 1u) ? s[j][1]*0.125f : -1e30f;
            s[j][2] = ((w1 >> sh) & 1u)     ? s[j][2]*0.125f : -1e30f;
            s[j][3] = ((w1 >> (sh+1)) & 1u) ? s[j][3]*0.125f : -1e30f;
        }

        // row max (quad reduce)
        float tm0 = -1e30f, tm1 = -1e30f;
        #pragma unroll
        for (int j = 0; j < 8; j++) {
            tm0 = fmaxf(tm0, fmaxf(s[j][0], s[j][1]));
            tm1 = fmaxf(tm1, fmaxf(s[j][2], s[j][3]));
        }
        tm0 = fmaxf(tm0, __shfl_xor_sync(0xffffffffu, tm0, 1));
        tm0 = fmaxf(tm0, __shfl_xor_sync(0xffffffffu, tm0, 2));
        tm1 = fmaxf(tm1, __shfl_xor_sync(0xffffffffu, tm1, 1));
        tm1 = fmaxf(tm1, __shfl_xor_sync(0xffffffffu, tm1, 2));

        float M0 = fmaxf(mrun0, tm0), M1 = fmaxf(mrun1, tm1);
        float a0 = fexp2((mrun0 - M0)*LOG2E);
        float a1 = fexp2((mrun1 - M1)*LOG2E);
        mrun0 = M0; mrun1 = M1;

        // p = exp(s - M), tile sums
        float ts0 = 0.f, ts1 = 0.f;
        #pragma unroll
        for (int j = 0; j < 8; j++) {
            s[j][0] = fexp2((s[j][0] - M0)*LOG2E);
            s[j][1] = fexp2((s[j][1] - M0)*LOG2E);
            s[j][2] = fexp2((s[j][2] - M1)*LOG2E);
            s[j][3] = fexp2((s[j][3] - M1)*LOG2E);
            ts0 += s[j][0] + s[j][1];
            ts1 += s[j][2] + s[j][3];
        }
        ts0 += __shfl_xor_sync(0xffffffffu, ts0, 1);
        ts0 += __shfl_xor_sync(0xffffffffu, ts0, 2);
        ts1 += __shfl_xor_sync(0xffffffffu, ts1, 1);
        ts1 += __shfl_xor_sync(0xffffffffu, ts1, 2);
        lrun0 = lrun0*a0 + ts0;
        lrun1 = lrun1*a1 + ts1;

        // rescale O
        #pragma unroll
        for (int j = 0; j < 8; j++) {
            o[j][0] *= a0; o[j][1] *= a0;
            o[j][2] *= a1; o[j][3] *= a1;
        }

        // pack P into fp16 A-fragments
        uint32_t pa[4][4];
        #pragma unroll
        for (int kk = 0; kk < 4; kk++) {
            pa[kk][0] = h2_as_u32(__floats2half2_rn(s[2*kk][0],   s[2*kk][1]));
            pa[kk][1] = h2_as_u32(__floats2half2_rn(s[2*kk][2],   s[2*kk][3]));
            pa[kk][2] = h2_as_u32(__floats2half2_rn(s[2*kk+1][0], s[2*kk+1][1]));
            pa[kk][3] = h2_as_u32(__floats2half2_rn(s[2*kk+1][2], s[2*kk+1][3]));
        }

        // O += P V   (B frags from V[key][d] via ldmatrix.trans)
        #pragma unroll
        for (int kk = 0; kk < 4; kk++) {
            #pragma unroll
            for (int dg = 0; dg < 4; dg++) {
                uint32_t vb[4];
                ldmx4t(vb, sVh + SMEM_SWIZZLE_128B(
                    (uint32_t)((kk*16 + lrow)*128 + dg*32) + lkhalf));
                mma16816h(o[2*dg],   pa[kk], vb[0], vb[1]);
                mma16816h(o[2*dg+1], pa[kk], vb[2], vb[3]);
            }
        }
        __syncthreads();
    }

    // finalize: divide by l, store to g_o (b, q, h*64+d)
    float inv0 = 1.f / fmaxf(lrun0, 1e-9f);
    float inv1 = 1.f / fmaxf(lrun1, 1e-9f);
    float* out0 = g_o + ((size_t)(b*Qn + q0 + r0))*(Hn*DHn) + h*DHn;
    float* out1 = g_o + ((size_t)(b*Qn + q0 + r1))*(Hn*DHn) + h*DHn;
    #pragma unroll
    for (int j = 0; j < 8; j++) {
        int d = j*8 + tg*2;
        *(float2*)(out0 + d) = make_float2(o[j][0]*inv0, o[j][1]*inv0);
        *(float2*)(out1 + d) = make_float2(o[j][2]*inv1, o[j][3]*inv1);
    }
}

// ---------------------------------------------------------------------------
extern "C" void kernel_launch(void* const* d_in, const int* in_sizes, int n_in,
                              void* d_out, int out_size)
{
    const float* x    = (const float*)d_in[0];
    const int*   mask = (const int*)d_in[1];
    const float* Wq   = (const float*)d_in[2];
    const float* Wk   = (const float*)d_in[3];
    const float* Wv   = (const float*)d_in[4];
    const float* Wo   = (const float*)d_in[5];
    const float* bo   = (const float*)d_in[6];
    float*       out  = (float*)d_out;

    cudaFuncSetAttribute(qkv_gemm_mma,
                         cudaFuncAttributeMaxDynamicSharedMemorySize, GEMM_SMEM_BYTES);
    cudaFuncSetAttribute(out_gemm_mma,
                         cudaFuncAttributeMaxDynamicSharedMemorySize, GEMM_SMEM_BYTES);
    cudaFuncSetAttribute(attn_mma,
                         cudaFuncAttributeMaxDynamicSharedMemorySize, ATTN_SMEM_BYTES);

    conv_split_x<<<8192, 256>>>(x);
    conv_w<<<dim3(32, 32, 4), 256>>>(Wq, Wk, Wv, Wo);
    pack_mask<<<2048, 256>>>(mask);

    qkv_gemm_mma<<<dim3(24, 64), 256, GEMM_SMEM_BYTES>>>();

    attn_mma<<<dim3(16, 64), 256, ATTN_SMEM_BYTES>>>();

    conv_split_o<<<8192, 256>>>();
    out_gemm_mma<<<dim3(8, 64), 256, GEMM_SMEM_BYTES>>>(bo, out);
}

// round 8
// speedup vs baseline: 2.8975x; 1.2474x over previous
#include <cuda_runtime.h>
#include <cuda_bf16.h>
#include <cuda_fp16.h>
#include <cstdint>

#define Bn  4
#define Qn  2048
#define Kn  2048
#define Dn  1024
#define Hn  16
#define DHn 64
#define BHn (Bn*Hn)

// ---------------------------------------------------------------------------
// Scratch (__device__ globals; cudaMalloc is forbidden)
// ---------------------------------------------------------------------------
__device__ float g_o[(size_t)Bn*Qn*Hn*DHn];          // attention out (b, q, h*64+d)

__device__ __half g_qhi[(size_t)BHn*Qn*DHn];
__device__ __half g_qlo[(size_t)BHn*Qn*DHn];
__device__ __half g_khi[(size_t)BHn*Kn*DHn];
__device__ __half g_klo[(size_t)BHn*Kn*DHn];
__device__ __half g_vh [(size_t)BHn*Kn*DHn];

__device__ uint32_t g_mbits[(size_t)Bn*Qn*64];

__device__ __nv_bfloat16 g_xhi[(size_t)8192*1024];
__device__ __nv_bfloat16 g_xlo[(size_t)8192*1024];
__device__ __nv_bfloat16 g_ohi[(size_t)8192*1024];
__device__ __nv_bfloat16 g_olo[(size_t)8192*1024];
__device__ __nv_bfloat16 g_wt_hi[(size_t)3072*1024];  // W_{q,k,v}^T  [n][k]
__device__ __nv_bfloat16 g_wt_lo[(size_t)3072*1024];
__device__ __nv_bfloat16 g_wot_hi[(size_t)1024*1024]; // Wo^T [n][k]
__device__ __nv_bfloat16 g_wot_lo[(size_t)1024*1024];

// ---------------------------------------------------------------------------
// helpers
// ---------------------------------------------------------------------------
__device__ __forceinline__ uint32_t smem_u32(const void* p) {
    uint32_t a;
    asm("{ .reg .u64 t; cvta.to.shared.u64 t, %1; cvt.u32.u64 %0, t; }"
        : "=r"(a) : "l"(p));
    return a;
}
__device__ __forceinline__ uint32_t h2_as_u32(__half2 v) {
    return *reinterpret_cast<uint32_t*>(&v);
}

#define SMEM_SWIZZLE_128B(byte_offset) \
    ((byte_offset) ^ (((byte_offset) >> 3) & 0x70))

__device__ __forceinline__ void cp_async16(uint32_t s_dst, const void* g_src) {
    asm volatile("cp.async.cg.shared.global [%0], [%1], 16;"
                 :: "r"(s_dst), "l"(g_src));
}
#define CP_COMMIT()  asm volatile("cp.async.commit_group;" ::: "memory")
#define CP_WAIT1()   asm volatile("cp.async.wait_group 1;" ::: "memory")
#define CP_WAIT2()   asm volatile("cp.async.wait_group 2;" ::: "memory")

__device__ __forceinline__ void ldmx4(uint32_t* r, uint32_t addr) {
    asm volatile("ldmatrix.sync.aligned.m8n8.x4.shared.b16 {%0,%1,%2,%3}, [%4];"
                 : "=r"(r[0]), "=r"(r[1]), "=r"(r[2]), "=r"(r[3]) : "r"(addr));
}
__device__ __forceinline__ void ldmx4t(uint32_t* r, uint32_t addr) {
    asm volatile("ldmatrix.sync.aligned.m8n8.x4.trans.shared.b16 {%0,%1,%2,%3}, [%4];"
                 : "=r"(r[0]), "=r"(r[1]), "=r"(r[2]), "=r"(r[3]) : "r"(addr));
}

__device__ __forceinline__ void mma16816(float* c, const uint32_t* a,
                                         uint32_t b0, uint32_t b1) {
    asm volatile(
        "mma.sync.aligned.m16n8k16.row.col.f32.bf16.bf16.f32 "
        "{%0,%1,%2,%3}, {%4,%5,%6,%7}, {%8,%9}, {%0,%1,%2,%3};"
        : "+f"(c[0]), "+f"(c[1]), "+f"(c[2]), "+f"(c[3])
        : "r"(a[0]), "r"(a[1]), "r"(a[2]), "r"(a[3]), "r"(b0), "r"(b1));
}
__device__ __forceinline__ void mma16816h(float* c, const uint32_t* a,
                                          uint32_t b0, uint32_t b1) {
    asm volatile(
        "mma.sync.aligned.m16n8k16.row.col.f32.f16.f16.f32 "
        "{%0,%1,%2,%3}, {%4,%5,%6,%7}, {%8,%9}, {%0,%1,%2,%3};"
        : "+f"(c[0]), "+f"(c[1]), "+f"(c[2]), "+f"(c[3])
        : "r"(a[0]), "r"(a[1]), "r"(a[2]), "r"(a[3]), "r"(b0), "r"(b1));
}

// fast exp2 (FFMA-only, rel err ~2.4e-6)
__device__ __forceinline__ float fexp2(float t) {
    t = fmaxf(t, -80.f);
    int i = __float2int_rn(t);
    float f = t - (float)i;
    float p = 1.3333558146e-3f;
    p = fmaf(p, f, 9.6181291057e-3f);
    p = fmaf(p, f, 5.5504108664e-2f);
    p = fmaf(p, f, 2.4022650696e-1f);
    p = fmaf(p, f, 6.9314718056e-1f);
    p = fmaf(p, f, 1.0f);
    return p * __int_as_float((i + 127) << 23);
}
#define LOG2E 1.4426950408889634f

// cp.async a 128-row x 128-byte tile into SW128 smem; ld_bytes = gmem row pitch
__device__ __forceinline__ void cp_tile128(uint32_t s_dst, const void* gbase,
                                           size_t ld_bytes, int tid) {
    const char* g = (const char*)gbase;
    #pragma unroll
    for (int i = 0; i < 4; i++) {
        int f = tid + 256*i;
        int row = f >> 3;
        int c16 = f & 7;
        uint32_t off = SMEM_SWIZZLE_128B((uint32_t)(row*128 + c16*16));
        cp_async16(s_dst + off, g + (size_t)row*ld_bytes + c16*16);
    }
}
// cp.async a 64-row x 128-byte tile (contiguous rows, 128B pitch)
__device__ __forceinline__ void cp_tile64(uint32_t s_dst, const void* gbase,
                                          int tid) {
    const char* g = (const char*)gbase;
    #pragma unroll
    for (int i = 0; i < 2; i++) {
        int f = tid + 256*i;
        int row = f >> 3;
        int c16 = f & 7;
        uint32_t off = SMEM_SWIZZLE_128B((uint32_t)(row*128 + c16*16));
        cp_async16(s_dst + off, g + (size_t)row*128 + c16*16);
    }
}

// ---------------------------------------------------------------------------
// Split-convert kernels: fp32 -> (bf16 hi, bf16 lo)
// ---------------------------------------------------------------------------
__device__ __forceinline__ void split4(float4 v, __nv_bfloat16* hi,
                                       __nv_bfloat16* lo, size_t idx) {
    float a[4] = {v.x, v.y, v.z, v.w};
    __nv_bfloat16 h[4], l[4];
    #pragma unroll
    for (int i = 0; i < 4; i++) {
        h[i] = __float2bfloat16(a[i]);
        l[i] = __float2bfloat16(a[i] - __bfloat162float(h[i]));
    }
    *(uint2*)(hi + idx) = *(uint2*)h;
    *(uint2*)(lo + idx) = *(uint2*)l;
}

__global__ void conv_split_x(const float* __restrict__ src) {
    size_t idx = ((size_t)blockIdx.x * 256 + threadIdx.x) * 4;
    split4(*(const float4*)(src + idx), g_xhi, g_xlo, idx);
}
__global__ void conv_split_o() {
    size_t idx = ((size_t)blockIdx.x * 256 + threadIdx.x) * 4;
    split4(*(const float4*)(g_o + idx), g_ohi, g_olo, idx);
}

// Transpose + split weights: W[k][n] (1024x1024) -> Wt[n][k] bf16 hi/lo
__global__ void conv_w(const float* __restrict__ Wq, const float* __restrict__ Wk,
                       const float* __restrict__ Wv, const float* __restrict__ Wo) {
    __shared__ float T[32][33];
    const float* src;
    __nv_bfloat16 *dh, *dl;
    int z = blockIdx.z;
    if      (z == 0) { src = Wq; dh = g_wt_hi;              dl = g_wt_lo; }
    else if (z == 1) { src = Wk; dh = g_wt_hi + 1024*1024;  dl = g_wt_lo + 1024*1024; }
    else if (z == 2) { src = Wv; dh = g_wt_hi + 2048*1024;  dl = g_wt_lo + 2048*1024; }
    else             { src = Wo; dh = g_wot_hi;             dl = g_wot_lo; }

    int n0 = blockIdx.x * 32, k0 = blockIdx.y * 32;
    int tx = threadIdx.x & 31, ty = threadIdx.x >> 5;
    #pragma unroll
    for (int i = 0; i < 4; i++)
        T[ty + 8*i][tx] = src[(size_t)(k0 + ty + 8*i) * 1024 + n0 + tx];
    __syncthreads();
    #pragma unroll
    for (int i = 0; i < 4; i++) {
        int n = n0 + ty + 8*i, k = k0 + tx;
        float v = T[tx][ty + 8*i];
        __nv_bfloat16 h = __float2bfloat16(v);
        dh[(size_t)n*1024 + k] = h;
        dl[(size_t)n*1024 + k] = __float2bfloat16(v - __bfloat162float(h));
    }
}

__global__ void pack_mask(const int* __restrict__ mask) {
    int warp = (blockIdx.x * blockDim.x + threadIdx.x) >> 5;
    int lane = threadIdx.x & 31;
    size_t base = (size_t)warp * 1024;
    #pragma unroll 4
    for (int r = 0; r < 32; r++) {
        int v = mask[base + r*32 + lane];
        unsigned bits = __ballot_sync(0xffffffffu, v != 0);
        if (lane == 0) g_mbits[(size_t)warp*32 + r] = bits;
    }
}

// ---------------------------------------------------------------------------
// mma.sync split-bf16 GEMM, cp.async double-buffered.
// 128x128 CTA tile, 8 warps (2m x 4n), warp 64x32. 2 stages x 64KB smem.
// ---------------------------------------------------------------------------
#define GSTG 65536
#define GEMM_SMEM_BYTES (2*GSTG)

struct GemmAcc { float a[4][4][4]; };

__device__ __forceinline__ void gemm_issue_stage(uint32_t sbuf,
                                                 const __nv_bfloat16* Ahi,
                                                 const __nv_bfloat16* Alo,
                                                 const __nv_bfloat16* Bhi,
                                                 const __nv_bfloat16* Blo,
                                                 int k0, int tid) {
    cp_tile128(sbuf,           Ahi + k0, 2048, tid);
    cp_tile128(sbuf + 16384,   Alo + k0, 2048, tid);
    cp_tile128(sbuf + 32768,   Bhi + k0, 2048, tid);
    cp_tile128(sbuf + 49152,   Blo + k0, 2048, tid);
}

__device__ __forceinline__ void gemm_mainloop_mma(uint32_t sb, GemmAcc& A,
                                                  const __nv_bfloat16* Ahi,
                                                  const __nv_bfloat16* Alo,
                                                  const __nv_bfloat16* Bhi,
                                                  const __nv_bfloat16* Blo,
                                                  int tid) {
    const int wid  = tid >> 5, lane = tid & 31;
    const int mw   = wid & 1, nw = wid >> 1;
    const uint32_t lrow  = lane & 15;
    const uint32_t lkoff = (lane >> 4) * 16;

    #pragma unroll
    for (int mi = 0; mi < 4; mi++)
        #pragma unroll
        for (int ni = 0; ni < 4; ni++)
            #pragma unroll
            for (int j = 0; j < 4; j++) A.a[mi][ni][j] = 0.f;

    gemm_issue_stage(sb,        Ahi, Alo, Bhi, Blo, 0,  tid);
    CP_COMMIT();
    gemm_issue_stage(sb + GSTG, Ahi, Alo, Bhi, Blo, 64, tid);
    CP_COMMIT();

    for (int st = 0; st < 16; st++) {
        CP_WAIT1();
        __syncthreads();

        const uint32_t sbuf = sb + (st & 1)*GSTG;
        const uint32_t sAh = sbuf, sAl = sbuf + 16384;
        const uint32_t sBh = sbuf + 32768, sBl = sbuf + 49152;

        #pragma unroll
        for (int ks = 0; ks < 4; ks++) {
            const uint32_t kb = ks*32 + lkoff;

            uint32_t ah[4][4];
            #pragma unroll
            for (int mi = 0; mi < 4; mi++)
                ldmx4(ah[mi], sAh + SMEM_SWIZZLE_128B(
                      (uint32_t)((mw*64 + mi*16 + lrow)*128) + kb));
            uint32_t bh[2][4];
            #pragma unroll
            for (int np = 0; np < 2; np++)
                ldmx4(bh[np], sBh + SMEM_SWIZZLE_128B(
                      (uint32_t)((nw*32 + np*16 + lrow)*128) + kb));

            #pragma unroll
            for (int mi = 0; mi < 4; mi++)
                #pragma unroll
                for (int ni = 0; ni < 4; ni++) {
                    int np = ni >> 1, s = ni & 1;
                    mma16816(A.a[mi][ni], ah[mi], bh[np][s], bh[np][s+2]);
                }

            uint32_t bl[2][4];
            #pragma unroll
            for (int np = 0; np < 2; np++)
                ldmx4(bl[np], sBl + SMEM_SWIZZLE_128B(
                      (uint32_t)((nw*32 + np*16 + lrow)*128) + kb));
            #pragma unroll
            for (int mi = 0; mi < 4; mi++)
                #pragma unroll
                for (int ni = 0; ni < 4; ni++) {
                    int np = ni >> 1, s = ni & 1;
                    mma16816(A.a[mi][ni], ah[mi], bl[np][s], bl[np][s+2]);
                }

            uint32_t al[4][4];
            #pragma unroll
            for (int mi = 0; mi < 4; mi++)
                ldmx4(al[mi], sAl + SMEM_SWIZZLE_128B(
                      (uint32_t)((mw*64 + mi*16 + lrow)*128) + kb));
            #pragma unroll
            for (int mi = 0; mi < 4; mi++)
                #pragma unroll
                for (int ni = 0; ni < 4; ni++) {
                    int np = ni >> 1, s = ni & 1;
                    mma16816(A.a[mi][ni], al[mi], bh[np][s], bh[np][s+2]);
                }
        }
        __syncthreads();

        if (st + 2 < 16)
            gemm_issue_stage(sb + (st & 1)*GSTG, Ahi, Alo, Bhi, Blo,
                             (st + 2)*64, tid);
        CP_COMMIT();
    }
}

__global__ __launch_bounds__(256)
void qkv_gemm_mma() {
    extern __shared__ char smem[];
    uint32_t sb = smem_u32(smem);
    int tid = threadIdx.x, lane = tid & 31, wid = tid >> 5;
    int mw = wid & 1, nw = wid >> 1;
    int n_base = blockIdx.x * 128;
    int m0 = blockIdx.y * 128;

    int kind;                      // 0=Q (hi/lo), 1=K (hi/lo), 2=V (fp16)
    if      (n_base < 1024) kind = 0;
    else if (n_base < 2048) kind = 1;
    else                    kind = 2;

    GemmAcc acc;
    gemm_mainloop_mma(sb, acc,
                      g_xhi + (size_t)m0*1024, g_xlo + (size_t)m0*1024,
                      g_wt_hi + (size_t)n_base*1024, g_wt_lo + (size_t)n_base*1024,
                      tid);

    int col_base = n_base & 1023;
    int g = lane >> 2, tg = lane & 3;
    #pragma unroll
    for (int mi = 0; mi < 4; mi++) {
        #pragma unroll
        for (int ni = 0; ni < 4; ni++) {
            int col = col_base + nw*32 + ni*8 + tg*2;
            int h = col >> 6, d = col & 63;
            #pragma unroll
            for (int half_ = 0; half_ < 2; half_++) {
                int m = m0 + mw*64 + mi*16 + g + half_*8;
                int bb = m >> 11, qp = m & 2047;
                float vx = acc.a[mi][ni][half_*2];
                float vy = acc.a[mi][ni][half_*2+1];
                size_t idx = (((size_t)(bb*Hn + h))*Qn + qp)*DHn + d;
                __half hx = __float2half_rn(vx), hy = __float2half_rn(vy);
                __half2 hh = __halves2half2(hx, hy);
                if (kind == 2) {
                    *(__half2*)&g_vh[idx] = hh;
                } else {
                    __half lx = __float2half_rn(vx - __half2float(hx));
                    __half ly = __float2half_rn(vy - __half2float(hy));
                    __half2 ll = __halves2half2(lx, ly);
                    if (kind == 0) {
                        *(__half2*)&g_qhi[idx] = hh;
                        *(__half2*)&g_qlo[idx] = ll;
                    } else {
                        *(__half2*)&g_khi[idx] = hh;
                        *(__half2*)&g_klo[idx] = ll;
                    }
                }
            }
        }
    }
}

__global__ __launch_bounds__(256)
void out_gemm_mma(const float* __restrict__ bo, float* __restrict__ out) {
    extern __shared__ char smem[];
    uint32_t sb = smem_u32(smem);
    int tid = threadIdx.x, lane = tid & 31, wid = tid >> 5;
    int mw = wid & 1, nw = wid >> 1;
    int n_base = blockIdx.x * 128;
    int m0 = blockIdx.y * 128;

    GemmAcc acc;
    gemm_mainloop_mma(sb, acc,
                      g_ohi + (size_t)m0*1024, g_olo + (size_t)m0*1024,
                      g_wot_hi + (size_t)n_base*1024, g_wot_lo + (size_t)n_base*1024,
                      tid);

    int g = lane >> 2, tg = lane & 3;
    #pragma unroll
    for (int ni = 0; ni < 4; ni++) {
        int n = n_base + nw*32 + ni*8 + tg*2;
        float2 bias = *(const float2*)&bo[n];
        #pragma unroll
        for (int mi = 0; mi < 4; mi++) {
            #pragma unroll
            for (int half_ = 0; half_ < 2; half_++) {
                int m = m0 + mw*64 + mi*16 + g + half_*8;
                float2 v = make_float2(acc.a[mi][ni][half_*2] + bias.x,
                                       acc.a[mi][ni][half_*2+1] + bias.y);
                *(float2*)&out[(size_t)m*1024 + n] = v;
            }
        }
    }
}

// ---------------------------------------------------------------------------
// Flash attention via mma.sync, cp.async double-buffered K/V.
// CTA = 128 q-rows of one (b,h); 8 warps; warp = 16 rows x 64-key tile.
// ---------------------------------------------------------------------------
#define ASTG 24576    // Kh(8K) + Kl(8K) + Vh(8K) per stage
#define ATTN_SMEM_BYTES (2*16384 + 2*ASTG)   // Qhi,Qlo + 2 KV stages

__device__ __forceinline__ void attn_issue_stage(uint32_t sbuf,
                                                 const __half* khp,
                                                 const __half* klp,
                                                 const __half* vhp,
                                                 int kt, int tid) {
    cp_tile64(sbuf,         khp + (size_t)kt*DHn, tid);
    cp_tile64(sbuf + 8192,  klp + (size_t)kt*DHn, tid);
    cp_tile64(sbuf + 16384, vhp + (size_t)kt*DHn, tid);
}

__global__ __launch_bounds__(256)
void attn_mma() {
    extern __shared__ char smem[];
    uint32_t sb = smem_u32(smem);
    const uint32_t sQh = sb;
    const uint32_t sQl = sQh + 16384;
    const uint32_t sKV = sQl + 16384;     // two ASTG stages

    const int tid = threadIdx.x;
    const int w = tid >> 5, lane = tid & 31;
    const int g = lane >> 2, tg = lane & 3;
    const uint32_t lrow = lane & 15;
    const uint32_t lkhalf = (lane >> 4) * 16;

    const int bh = blockIdx.y;
    const int b = bh >> 4, h = bh & 15;
    const int q0 = blockIdx.x * 128;

    const __half* qhp = g_qhi + ((size_t)bh*Qn + q0)*DHn;
    const __half* qlp = g_qlo + ((size_t)bh*Qn + q0)*DHn;
    const __half* khp = g_khi + (size_t)bh*Kn*DHn;
    const __half* klp = g_klo + (size_t)bh*Kn*DHn;
    const __half* vhp = g_vh  + (size_t)bh*Kn*DHn;

    // group 0: Q tiles (row pitch = 64 halves = 128 bytes)
    cp_tile128(sQh, qhp, 128, tid);
    cp_tile128(sQl, qlp, 128, tid);
    CP_COMMIT();
    attn_issue_stage(sKV,        khp, klp, vhp, 0,  tid);
    CP_COMMIT();
    attn_issue_stage(sKV + ASTG, khp, klp, vhp, 64, tid);
    CP_COMMIT();

    // Q ready after wait(2)
    CP_WAIT2();
    __syncthreads();

    uint32_t qh[4][4], ql[4][4];
    #pragma unroll
    for (int ks = 0; ks < 4; ks++) {
        uint32_t kb = ks*32 + lkhalf;
        uint32_t roff = SMEM_SWIZZLE_128B((uint32_t)((w*16 + lrow)*128) + kb);
        ldmx4(qh[ks], sQh + roff);
        ldmx4(ql[ks], sQl + roff);
    }

    float o[8][4];
    #pragma unroll
    for (int j = 0; j < 8; j++)
        #pragma unroll
        for (int c = 0; c < 4; c++) o[j][c] = 0.f;
    float mrun0 = -1e30f, mrun1 = -1e30f;
    float lrun0 = 0.f, lrun1 = 0.f;

    const int r0 = w*16 + g;
    const int r1 = r0 + 8;
    const uint32_t* mb0 = g_mbits + ((size_t)b*Qn + q0 + r0)*64;
    const uint32_t* mb1 = g_mbits + ((size_t)b*Qn + q0 + r1)*64;

    for (int it = 0; it < 32; it++) {
        CP_WAIT1();
        __syncthreads();

        const uint32_t sbuf = sKV + (it & 1)*ASTG;
        const uint32_t sKh = sbuf, sKl = sbuf + 8192, sVh = sbuf + 16384;

        // S = Q K^T  (split-fp16, 3 products)
        float s[8][4];
        #pragma unroll
        for (int j = 0; j < 8; j++)
            #pragma unroll
            for (int c = 0; c < 4; c++) s[j][c] = 0.f;

        #pragma unroll
        for (int ks = 0; ks < 4; ks++) {
            uint32_t kb = ks*32 + lkhalf;
            #pragma unroll
            for (int kg = 0; kg < 4; kg++) {
                uint32_t roff = SMEM_SWIZZLE_128B(
                    (uint32_t)((kg*16 + lrow)*128) + kb);
                uint32_t bh_[4], bl_[4];
                ldmx4(bh_, sKh + roff);
                ldmx4(bl_, sKl + roff);
                #pragma unroll
                for (int s2 = 0; s2 < 2; s2++) {
                    int j = 2*kg + s2;
                    mma16816h(s[j], qh[ks], bh_[s2], bh_[s2+2]);
                    mma16816h(s[j], ql[ks], bh_[s2], bh_[s2+2]);
                    mma16816h(s[j], qh[ks], bl_[s2], bl_[s2+2]);
                }
            }
        }

        // mask + scale
        int kt = it * 64;
        uint2 mw0 = *(const uint2*)(mb0 + (kt >> 5));
        uint2 mw1 = *(const uint2*)(mb1 + (kt >> 5));
        #pragma unroll
        for (int j = 0; j < 8; j++) {
            int c = j*8 + tg*2;
            uint32_t w0 = (c & 32) ? mw0.y : mw0.x;
            uint32_t w1 = (c & 32) ? mw1.y : mw1.x;
            int sh = c & 31;
            s[j][0] = ((w0 >> sh) & 1u)     ? s[j][0]*0.125f : -1e30f;
            s[j][1] = ((w0 >> (sh+1)) & 1u) ? s[j][1]*0.125f : -1e30f;
            s[j][2] = ((w1 >> sh) & 1u)     ? s[j][2]*0.125f : -1e30f;
            s[j][3] = ((w1 >> (sh+1)) & 1u) ? s[j][3]*0.125f : -1e30f;
        }

        // row max (quad reduce)
        float tm0 = -1e30f, tm1 = -1e30f;
        #pragma unroll
        for (int j = 0; j < 8; j++) {
            tm0 = fmaxf(tm0, fmaxf(s[j][0], s[j][1]));
            tm1 = fmaxf(tm1, fmaxf(s[j][2], s[j][3]));
        }
        tm0 = fmaxf(tm0, __shfl_xor_sync(0xffffffffu, tm0, 1));
        tm0 = fmaxf(tm0, __shfl_xor_sync(0xffffffffu, tm0, 2));
        tm1 = fmaxf(tm1, __shfl_xor_sync(0xffffffffu, tm1, 1));
        tm1 = fmaxf(tm1, __shfl_xor_sync(0xffffffffu, tm1, 2));

        float M0 = fmaxf(mrun0, tm0), M1 = fmaxf(mrun1, tm1);
        float a0 = fexp2((mrun0 - M0)*LOG2E);
        float a1 = fexp2((mrun1 - M1)*LOG2E);
        mrun0 = M0; mrun1 = M1;

        float ts0 = 0.f, ts1 = 0.f;
        #pragma unroll
        for (int j = 0; j < 8; j++) {
            s[j][0] = fexp2((s[j][0] - M0)*LOG2E);
            s[j][1] = fexp2((s[j][1] - M0)*LOG2E);
            s[j][2] = fexp2((s[j][2] - M1)*LOG2E);
            s[j][3] = fexp2((s[j][3] - M1)*LOG2E);
            ts0 += s[j][0] + s[j][1];
            ts1 += s[j][2] + s[j][3];
        }
        ts0 += __shfl_xor_sync(0xffffffffu, ts0, 1);
        ts0 += __shfl_xor_sync(0xffffffffu, ts0, 2);
        ts1 += __shfl_xor_sync(0xffffffffu, ts1, 1);
        ts1 += __shfl_xor_sync(0xffffffffu, ts1, 2);
        lrun0 = lrun0*a0 + ts0;
        lrun1 = lrun1*a1 + ts1;

        #pragma unroll
        for (int j = 0; j < 8; j++) {
            o[j][0] *= a0; o[j][1] *= a0;
            o[j][2] *= a1; o[j][3] *= a1;
        }

        uint32_t pa[4][4];
        #pragma unroll
        for (int kk = 0; kk < 4; kk++) {
            pa[kk][0] = h2_as_u32(__floats2half2_rn(s[2*kk][0],   s[2*kk][1]));
            pa[kk][1] = h2_as_u32(__floats2half2_rn(s[2*kk][2],   s[2*kk][3]));
            pa[kk][2] = h2_as_u32(__floats2half2_rn(s[2*kk+1][0], s[2*kk+1][1]));
            pa[kk][3] = h2_as_u32(__floats2half2_rn(s[2*kk+1][2], s[2*kk+1][3]));
        }

        #pragma unroll
        for (int kk = 0; kk < 4; kk++) {
            #pragma unroll
            for (int dg = 0; dg < 4; dg++) {
                uint32_t vb[4];
                ldmx4t(vb, sVh + SMEM_SWIZZLE_128B(
                    (uint32_t)((kk*16 + lrow)*128 + dg*32) + lkhalf));
                mma16816h(o[2*dg],   pa[kk], vb[0], vb[1]);
                mma16816h(o[2*dg+1], pa[kk], vb[2], vb[3]);
            }
        }
        __syncthreads();

        if (it + 2 < 32)
            attn_issue_stage(sKV + (it & 1)*ASTG, khp, klp, vhp,
                             (it + 2)*64, tid);
        CP_COMMIT();
    }

    float inv0 = 1.f / fmaxf(lrun0, 1e-9f);
    float inv1 = 1.f / fmaxf(lrun1, 1e-9f);
    float* out0 = g_o + ((size_t)(b*Qn + q0 + r0))*(Hn*DHn) + h*DHn;
    float* out1 = g_o + ((size_t)(b*Qn + q0 + r1))*(Hn*DHn) + h*DHn;
    #pragma unroll
    for (int j = 0; j < 8; j++) {
        int d = j*8 + tg*2;
        *(float2*)(out0 + d) = make_float2(o[j][0]*inv0, o[j][1]*inv0);
        *(float2*)(out1 + d) = make_float2(o[j][2]*inv1, o[j][3]*inv1);
    }
}

// ---------------------------------------------------------------------------
extern "C" void kernel_launch(void* const* d_in, const int* in_sizes, int n_in,
                              void* d_out, int out_size)
{
    const float* x    = (const float*)d_in[0];
    const int*   mask = (const int*)d_in[1];
    const float* Wq   = (const float*)d_in[2];
    const float* Wk   = (const float*)d_in[3];
    const float* Wv   = (const float*)d_in[4];
    const float* Wo   = (const float*)d_in[5];
    const float* bo   = (const float*)d_in[6];
    float*       out  = (float*)d_out;

    cudaFuncSetAttribute(qkv_gemm_mma,
                         cudaFuncAttributeMaxDynamicSharedMemorySize, GEMM_SMEM_BYTES);
    cudaFuncSetAttribute(out_gemm_mma,
                         cudaFuncAttributeMaxDynamicSharedMemorySize, GEMM_SMEM_BYTES);
    cudaFuncSetAttribute(attn_mma,
                         cudaFuncAttributeMaxDynamicSharedMemorySize, ATTN_SMEM_BYTES);

    conv_split_x<<<8192, 256>>>(x);
    conv_w<<<dim3(32, 32, 4), 256>>>(Wq, Wk, Wv, Wo);
    pack_mask<<<2048, 256>>>(mask);

    qkv_gemm_mma<<<dim3(24, 64), 256, GEMM_SMEM_BYTES>>>();

    attn_mma<<<dim3(16, 64), 256, ATTN_SMEM_BYTES>>>();

    conv_split_o<<<8192, 256>>>();
    out_gemm_mma<<<dim3(8, 64), 256, GEMM_SMEM_BYTES>>>(bo, out);
}

// round 9
// speedup vs baseline: 2.9364x; 1.0134x over previous
#include <cuda_runtime.h>
#include <cuda_bf16.h>
#include <cuda_fp16.h>
#include <cstdint>

#define Bn  4
#define Qn  2048
#define Kn  2048
#define Dn  1024
#define Hn  16
#define DHn 64
#define BHn (Bn*Hn)

// ---------------------------------------------------------------------------
// Scratch (__device__ globals; cudaMalloc is forbidden)
// ---------------------------------------------------------------------------
__device__ __half g_qhi[(size_t)BHn*Qn*DHn];
__device__ __half g_qlo[(size_t)BHn*Qn*DHn];
__device__ __half g_khi[(size_t)BHn*Kn*DHn];
__device__ __half g_klo[(size_t)BHn*Kn*DHn];
__device__ __half g_vh [(size_t)BHn*Kn*DHn];

__device__ uint32_t g_mbits[(size_t)Bn*Qn*64];

__device__ __nv_bfloat16 g_xhi[(size_t)8192*1024];
__device__ __nv_bfloat16 g_xlo[(size_t)8192*1024];
__device__ __nv_bfloat16 g_ohi[(size_t)8192*1024];   // attn out split (b,q,h*64+d)
__device__ __nv_bfloat16 g_olo[(size_t)8192*1024];
__device__ __nv_bfloat16 g_wt_hi[(size_t)3072*1024];  // W_{q,k,v}^T  [n][k]
__device__ __nv_bfloat16 g_wt_lo[(size_t)3072*1024];
__device__ __nv_bfloat16 g_wot_hi[(size_t)1024*1024]; // Wo^T [n][k]
__device__ __nv_bfloat16 g_wot_lo[(size_t)1024*1024];

// ---------------------------------------------------------------------------
// helpers
// ---------------------------------------------------------------------------
__device__ __forceinline__ uint32_t smem_u32(const void* p) {
    uint32_t a;
    asm("{ .reg .u64 t; cvta.to.shared.u64 t, %1; cvt.u32.u64 %0, t; }"
        : "=r"(a) : "l"(p));
    return a;
}
__device__ __forceinline__ uint32_t h2_as_u32(__half2 v) {
    return *reinterpret_cast<uint32_t*>(&v);
}

#define SMEM_SWIZZLE_128B(byte_offset) \
    ((byte_offset) ^ (((byte_offset) >> 3) & 0x70))

__device__ __forceinline__ void cp_async16(uint32_t s_dst, const void* g_src) {
    asm volatile("cp.async.cg.shared.global [%0], [%1], 16;"
                 :: "r"(s_dst), "l"(g_src));
}
#define CP_COMMIT()  asm volatile("cp.async.commit_group;" ::: "memory")
#define CP_WAIT1()   asm volatile("cp.async.wait_group 1;" ::: "memory")
#define CP_WAIT2()   asm volatile("cp.async.wait_group 2;" ::: "memory")

__device__ __forceinline__ void ldmx4(uint32_t* r, uint32_t addr) {
    asm volatile("ldmatrix.sync.aligned.m8n8.x4.shared.b16 {%0,%1,%2,%3}, [%4];"
                 : "=r"(r[0]), "=r"(r[1]), "=r"(r[2]), "=r"(r[3]) : "r"(addr));
}
__device__ __forceinline__ void ldmx4t(uint32_t* r, uint32_t addr) {
    asm volatile("ldmatrix.sync.aligned.m8n8.x4.trans.shared.b16 {%0,%1,%2,%3}, [%4];"
                 : "=r"(r[0]), "=r"(r[1]), "=r"(r[2]), "=r"(r[3]) : "r"(addr));
}

__device__ __forceinline__ void mma16816(float* c, const uint32_t* a,
                                         uint32_t b0, uint32_t b1) {
    asm volatile(
        "mma.sync.aligned.m16n8k16.row.col.f32.bf16.bf16.f32 "
        "{%0,%1,%2,%3}, {%4,%5,%6,%7}, {%8,%9}, {%0,%1,%2,%3};"
        : "+f"(c[0]), "+f"(c[1]), "+f"(c[2]), "+f"(c[3])
        : "r"(a[0]), "r"(a[1]), "r"(a[2]), "r"(a[3]), "r"(b0), "r"(b1));
}
__device__ __forceinline__ void mma16816h(float* c, const uint32_t* a,
                                          uint32_t b0, uint32_t b1) {
    asm volatile(
        "mma.sync.aligned.m16n8k16.row.col.f32.f16.f16.f32 "
        "{%0,%1,%2,%3}, {%4,%5,%6,%7}, {%8,%9}, {%0,%1,%2,%3};"
        : "+f"(c[0]), "+f"(c[1]), "+f"(c[2]), "+f"(c[3])
        : "r"(a[0]), "r"(a[1]), "r"(a[2]), "r"(a[3]), "r"(b0), "r"(b1));
}

// fast exp2 (FFMA-only, rel err ~2.4e-6)
__device__ __forceinline__ float fexp2(float t) {
    t = fmaxf(t, -80.f);
    int i = __float2int_rn(t);
    float f = t - (float)i;
    float p = 1.3333558146e-3f;
    p = fmaf(p, f, 9.6181291057e-3f);
    p = fmaf(p, f, 5.5504108664e-2f);
    p = fmaf(p, f, 2.4022650696e-1f);
    p = fmaf(p, f, 6.9314718056e-1f);
    p = fmaf(p, f, 1.0f);
    return p * __int_as_float((i + 127) << 23);
}
#define LOG2E 1.4426950408889634f

// cp.async a 128-row x 128-byte tile into SW128 smem; ld_bytes = gmem row pitch
__device__ __forceinline__ void cp_tile128(uint32_t s_dst, const void* gbase,
                                           size_t ld_bytes, int tid) {
    const char* g = (const char*)gbase;
    #pragma unroll
    for (int i = 0; i < 4; i++) {
        int f = tid + 256*i;
        int row = f >> 3;
        int c16 = f & 7;
        uint32_t off = SMEM_SWIZZLE_128B((uint32_t)(row*128 + c16*16));
        cp_async16(s_dst + off, g + (size_t)row*ld_bytes + c16*16);
    }
}
// cp.async a 64-row x 128-byte tile (contiguous rows, 128B pitch)
__device__ __forceinline__ void cp_tile64(uint32_t s_dst, const void* gbase,
                                          int tid) {
    const char* g = (const char*)gbase;
    #pragma unroll
    for (int i = 0; i < 2; i++) {
        int f = tid + 256*i;
        int row = f >> 3;
        int c16 = f & 7;
        uint32_t off = SMEM_SWIZZLE_128B((uint32_t)(row*128 + c16*16));
        cp_async16(s_dst + off, g + (size_t)row*128 + c16*16);
    }
}

// ---------------------------------------------------------------------------
// Split-convert kernels: fp32 -> (bf16 hi, bf16 lo)
// ---------------------------------------------------------------------------
__device__ __forceinline__ void split4(float4 v, __nv_bfloat16* hi,
                                       __nv_bfloat16* lo, size_t idx) {
    float a[4] = {v.x, v.y, v.z, v.w};
    __nv_bfloat16 h[4], l[4];
    #pragma unroll
    for (int i = 0; i < 4; i++) {
        h[i] = __float2bfloat16(a[i]);
        l[i] = __float2bfloat16(a[i] - __bfloat162float(h[i]));
    }
    *(uint2*)(hi + idx) = *(uint2*)h;
    *(uint2*)(lo + idx) = *(uint2*)l;
}

__global__ void conv_split_x(const float* __restrict__ src) {
    size_t idx = ((size_t)blockIdx.x * 256 + threadIdx.x) * 4;
    split4(*(const float4*)(src + idx), g_xhi, g_xlo, idx);
}

// Transpose + split weights: W[k][n] (1024x1024) -> Wt[n][k] bf16 hi/lo
__global__ void conv_w(const float* __restrict__ Wq, const float* __restrict__ Wk,
                       const float* __restrict__ Wv, const float* __restrict__ Wo) {
    __shared__ float T[32][33];
    const float* src;
    __nv_bfloat16 *dh, *dl;
    int z = blockIdx.z;
    if      (z == 0) { src = Wq; dh = g_wt_hi;              dl = g_wt_lo; }
    else if (z == 1) { src = Wk; dh = g_wt_hi + 1024*1024;  dl = g_wt_lo + 1024*1024; }
    else if (z == 2) { src = Wv; dh = g_wt_hi + 2048*1024;  dl = g_wt_lo + 2048*1024; }
    else             { src = Wo; dh = g_wot_hi;             dl = g_wot_lo; }

    int n0 = blockIdx.x * 32, k0 = blockIdx.y * 32;
    int tx = threadIdx.x & 31, ty = threadIdx.x >> 5;
    #pragma unroll
    for (int i = 0; i < 4; i++)
        T[ty + 8*i][tx] = src[(size_t)(k0 + ty + 8*i) * 1024 + n0 + tx];
    __syncthreads();
    #pragma unroll
    for (int i = 0; i < 4; i++) {
        int n = n0 + ty + 8*i, k = k0 + tx;
        float v = T[tx][ty + 8*i];
        __nv_bfloat16 h = __float2bfloat16(v);
        dh[(size_t)n*1024 + k] = h;
        dl[(size_t)n*1024 + k] = __float2bfloat16(v - __bfloat162float(h));
    }
}

__global__ void pack_mask(const int* __restrict__ mask) {
    int warp = (blockIdx.x * blockDim.x + threadIdx.x) >> 5;
    int lane = threadIdx.x & 31;
    size_t base = (size_t)warp * 1024;
    #pragma unroll 4
    for (int r = 0; r < 32; r++) {
        int v = mask[base + r*32 + lane];
        unsigned bits = __ballot_sync(0xffffffffu, v != 0);
        if (lane == 0) g_mbits[(size_t)warp*32 + r] = bits;
    }
}

// ---------------------------------------------------------------------------
// mma.sync split-bf16 GEMM, cp.async 3-stage pipelined (issue-before-compute).
// 128x128 CTA tile, 8 warps (2m x 4n), warp 64x32. 3 stages x 64KB smem.
// ---------------------------------------------------------------------------
#define GSTG 65536
#define GEMM_SMEM_BYTES (3*GSTG)

struct GemmAcc { float a[4][4][4]; };

__device__ __forceinline__ void gemm_issue_stage(uint32_t sbuf,
                                                 const __nv_bfloat16* Ahi,
                                                 const __nv_bfloat16* Alo,
                                                 const __nv_bfloat16* Bhi,
                                                 const __nv_bfloat16* Blo,
                                                 int k0, int tid) {
    cp_tile128(sbuf,           Ahi + k0, 2048, tid);
    cp_tile128(sbuf + 16384,   Alo + k0, 2048, tid);
    cp_tile128(sbuf + 32768,   Bhi + k0, 2048, tid);
    cp_tile128(sbuf + 49152,   Blo + k0, 2048, tid);
}

__device__ __forceinline__ void gemm_mainloop_mma(uint32_t sb, GemmAcc& A,
                                                  const __nv_bfloat16* Ahi,
                                                  const __nv_bfloat16* Alo,
                                                  const __nv_bfloat16* Bhi,
                                                  const __nv_bfloat16* Blo,
                                                  int tid) {
    const int wid  = tid >> 5, lane = tid & 31;
    const int mw   = wid & 1, nw = wid >> 1;
    const uint32_t lrow  = lane & 15;
    const uint32_t lkoff = (lane >> 4) * 16;

    #pragma unroll
    for (int mi = 0; mi < 4; mi++)
        #pragma unroll
        for (int ni = 0; ni < 4; ni++)
            #pragma unroll
            for (int j = 0; j < 4; j++) A.a[mi][ni][j] = 0.f;

    gemm_issue_stage(sb,        Ahi, Alo, Bhi, Blo, 0,  tid);
    CP_COMMIT();
    gemm_issue_stage(sb + GSTG, Ahi, Alo, Bhi, Blo, 64, tid);
    CP_COMMIT();

    int buf = 0;            // buffer of stage st
    int nbuf = 2;           // buffer to fill next
    for (int st = 0; st < 16; st++) {
        CP_WAIT1();         // stage st landed
        __syncthreads();

        // issue stage st+2 into the buffer freed at st-1 (safe: sync above)
        if (st + 2 < 16)
            gemm_issue_stage(sb + nbuf*GSTG, Ahi, Alo, Bhi, Blo,
                             (st + 2)*64, tid);
        CP_COMMIT();

        const uint32_t sbuf = sb + buf*GSTG;
        const uint32_t sAh = sbuf, sAl = sbuf + 16384;
        const uint32_t sBh = sbuf + 32768, sBl = sbuf + 49152;

        #pragma unroll
        for (int ks = 0; ks < 4; ks++) {
            const uint32_t kb = ks*32 + lkoff;

            uint32_t ah[4][4];
            #pragma unroll
            for (int mi = 0; mi < 4; mi++)
                ldmx4(ah[mi], sAh + SMEM_SWIZZLE_128B(
                      (uint32_t)((mw*64 + mi*16 + lrow)*128) + kb));
            uint32_t bh[2][4];
            #pragma unroll
            for (int np = 0; np < 2; np++)
                ldmx4(bh[np], sBh + SMEM_SWIZZLE_128B(
                      (uint32_t)((nw*32 + np*16 + lrow)*128) + kb));

            #pragma unroll
            for (int mi = 0; mi < 4; mi++)
                #pragma unroll
                for (int ni = 0; ni < 4; ni++) {
                    int np = ni >> 1, s = ni & 1;
                    mma16816(A.a[mi][ni], ah[mi], bh[np][s], bh[np][s+2]);
                }

            uint32_t bl[2][4];
            #pragma unroll
            for (int np = 0; np < 2; np++)
                ldmx4(bl[np], sBl + SMEM_SWIZZLE_128B(
                      (uint32_t)((nw*32 + np*16 + lrow)*128) + kb));
            #pragma unroll
            for (int mi = 0; mi < 4; mi++)
                #pragma unroll
                for (int ni = 0; ni < 4; ni++) {
                    int np = ni >> 1, s = ni & 1;
                    mma16816(A.a[mi][ni], ah[mi], bl[np][s], bl[np][s+2]);
                }

            uint32_t al[4][4];
            #pragma unroll
            for (int mi = 0; mi < 4; mi++)
                ldmx4(al[mi], sAl + SMEM_SWIZZLE_128B(
                      (uint32_t)((mw*64 + mi*16 + lrow)*128) + kb));
            #pragma unroll
            for (int mi = 0; mi < 4; mi++)
                #pragma unroll
                for (int ni = 0; ni < 4; ni++) {
                    int np = ni >> 1, s = ni & 1;
                    mma16816(A.a[mi][ni], al[mi], bh[np][s], bh[np][s+2]);
                }
        }

        buf = (buf + 1 == 3) ? 0 : buf + 1;
        nbuf = (nbuf + 1 == 3) ? 0 : nbuf + 1;
    }
}

__global__ __launch_bounds__(256)
void qkv_gemm_mma() {
    extern __shared__ char smem[];
    uint32_t sb = smem_u32(smem);
    int tid = threadIdx.x, lane = tid & 31, wid = tid >> 5;
    int mw = wid & 1, nw = wid >> 1;
    int n_base = blockIdx.x * 128;
    int m0 = blockIdx.y * 128;

    int kind;                      // 0=Q (hi/lo), 1=K (hi/lo), 2=V (fp16)
    if      (n_base < 1024) kind = 0;
    else if (n_base < 2048) kind = 1;
    else                    kind = 2;

    GemmAcc acc;
    gemm_mainloop_mma(sb, acc,
                      g_xhi + (size_t)m0*1024, g_xlo + (size_t)m0*1024,
                      g_wt_hi + (size_t)n_base*1024, g_wt_lo + (size_t)n_base*1024,
                      tid);

    int col_base = n_base & 1023;
    int g = lane >> 2, tg = lane & 3;
    #pragma unroll
    for (int mi = 0; mi < 4; mi++) {
        #pragma unroll
        for (int ni = 0; ni < 4; ni++) {
            int col = col_base + nw*32 + ni*8 + tg*2;
            int h = col >> 6, d = col & 63;
            #pragma unroll
            for (int half_ = 0; half_ < 2; half_++) {
                int m = m0 + mw*64 + mi*16 + g + half_*8;
                int bb = m >> 11, qp = m & 2047;
                float vx = acc.a[mi][ni][half_*2];
                float vy = acc.a[mi][ni][half_*2+1];
                size_t idx = (((size_t)(bb*Hn + h))*Qn + qp)*DHn + d;
                __half hx = __float2half_rn(vx), hy = __float2half_rn(vy);
                __half2 hh = __halves2half2(hx, hy);
                if (kind == 2) {
                    *(__half2*)&g_vh[idx] = hh;
                } else {
                    __half lx = __float2half_rn(vx - __half2float(hx));
                    __half ly = __float2half_rn(vy - __half2float(hy));
                    __half2 ll = __halves2half2(lx, ly);
                    if (kind == 0) {
                        *(__half2*)&g_qhi[idx] = hh;
                        *(__half2*)&g_qlo[idx] = ll;
                    } else {
                        *(__half2*)&g_khi[idx] = hh;
                        *(__half2*)&g_klo[idx] = ll;
                    }
                }
            }
        }
    }
}

__global__ __launch_bounds__(256)
void out_gemm_mma(const float* __restrict__ bo, float* __restrict__ out) {
    extern __shared__ char smem[];
    uint32_t sb = smem_u32(smem);
    int tid = threadIdx.x, lane = tid & 31, wid = tid >> 5;
    int mw = wid & 1, nw = wid >> 1;
    int n_base = blockIdx.x * 128;
    int m0 = blockIdx.y * 128;

    GemmAcc acc;
    gemm_mainloop_mma(sb, acc,
                      g_ohi + (size_t)m0*1024, g_olo + (size_t)m0*1024,
                      g_wot_hi + (size_t)n_base*1024, g_wot_lo + (size_t)n_base*1024,
                      tid);

    int g = lane >> 2, tg = lane & 3;
    #pragma unroll
    for (int ni = 0; ni < 4; ni++) {
        int n = n_base + nw*32 + ni*8 + tg*2;
        float2 bias = *(const float2*)&bo[n];
        #pragma unroll
        for (int mi = 0; mi < 4; mi++) {
            #pragma unroll
            for (int half_ = 0; half_ < 2; half_++) {
                int m = m0 + mw*64 + mi*16 + g + half_*8;
                float2 v = make_float2(acc.a[mi][ni][half_*2] + bias.x,
                                       acc.a[mi][ni][half_*2+1] + bias.y);
                *(float2*)&out[(size_t)m*1024 + n] = v;
            }
        }
    }
}

// ---------------------------------------------------------------------------
// Flash attention via mma.sync, cp.async 3-stage KV pipeline, 2 CTAs/SM.
// CTA = 128 q-rows of one (b,h); 8 warps; warp = 16 rows x 64-key tile.
// Epilogue writes bf16 hi/lo directly (fused conv_split_o).
// ---------------------------------------------------------------------------
#define ASTG 24576    // Kh(8K) + Kl(8K) + Vh(8K) per stage
#define ATTN_SMEM_BYTES (2*16384 + 3*ASTG)   // Qhi,Qlo + 3 KV stages = 104KB

__device__ __forceinline__ void attn_issue_stage(uint32_t sbuf,
                                                 const __half* khp,
                                                 const __half* klp,
                                                 const __half* vhp,
                                                 int kt, int tid) {
    cp_tile64(sbuf,         khp + (size_t)kt*DHn, tid);
    cp_tile64(sbuf + 8192,  klp + (size_t)kt*DHn, tid);
    cp_tile64(sbuf + 16384, vhp + (size_t)kt*DHn, tid);
}

__global__ __launch_bounds__(256, 2)
void attn_mma() {
    extern __shared__ char smem[];
    uint32_t sb = smem_u32(smem);
    const uint32_t sQh = sb;
    const uint32_t sQl = sQh + 16384;
    const uint32_t sKV = sQl + 16384;     // three ASTG stages

    const int tid = threadIdx.x;
    const int w = tid >> 5, lane = tid & 31;
    const int g = lane >> 2, tg = lane & 3;
    const uint32_t lrow = lane & 15;
    const uint32_t lkhalf = (lane >> 4) * 16;

    const int bh = blockIdx.y;
    const int b = bh >> 4, h = bh & 15;
    const int q0 = blockIdx.x * 128;

    const __half* qhp = g_qhi + ((size_t)bh*Qn + q0)*DHn;
    const __half* qlp = g_qlo + ((size_t)bh*Qn + q0)*DHn;
    const __half* khp = g_khi + (size_t)bh*Kn*DHn;
    const __half* klp = g_klo + (size_t)bh*Kn*DHn;
    const __half* vhp = g_vh  + (size_t)bh*Kn*DHn;

    // g0: Q tiles; g1: KV0; g2: KV1
    cp_tile128(sQh, qhp, 128, tid);
    cp_tile128(sQl, qlp, 128, tid);
    CP_COMMIT();
    attn_issue_stage(sKV,          khp, klp, vhp, 0,   tid);
    CP_COMMIT();
    attn_issue_stage(sKV + ASTG,   khp, klp, vhp, 64,  tid);
    CP_COMMIT();

    // Q landed after wait(2)
    CP_WAIT2();
    __syncthreads();

    uint32_t qh[4][4], ql[4][4];
    #pragma unroll
    for (int ks = 0; ks < 4; ks++) {
        uint32_t kb = ks*32 + lkhalf;
        uint32_t roff = SMEM_SWIZZLE_128B((uint32_t)((w*16 + lrow)*128) + kb);
        ldmx4(qh[ks], sQh + roff);
        ldmx4(ql[ks], sQl + roff);
    }

    float o[8][4];
    #pragma unroll
    for (int j = 0; j < 8; j++)
        #pragma unroll
        for (int c = 0; c < 4; c++) o[j][c] = 0.f;
    float mrun0 = -1e30f, mrun1 = -1e30f;
    float lrun0 = 0.f, lrun1 = 0.f;

    const int r0 = w*16 + g;
    const int r1 = r0 + 8;
    const uint32_t* mb0 = g_mbits + ((size_t)b*Qn + q0 + r0)*64;
    const uint32_t* mb1 = g_mbits + ((size_t)b*Qn + q0 + r1)*64;

    int buf = 0, nbuf = 2;
    for (int it = 0; it < 32; it++) {
        CP_WAIT1();           // KV_it landed
        __syncthreads();

        if (it + 2 < 32)
            attn_issue_stage(sKV + nbuf*ASTG, khp, klp, vhp,
                             (it + 2)*64, tid);
        CP_COMMIT();

        const uint32_t sbuf = sKV + buf*ASTG;
        const uint32_t sKh = sbuf, sKl = sbuf + 8192, sVh = sbuf + 16384;

        // S = Q K^T  (split-fp16, 3 products)
        float s[8][4];
        #pragma unroll
        for (int j = 0; j < 8; j++)
            #pragma unroll
            for (int c = 0; c < 4; c++) s[j][c] = 0.f;

        #pragma unroll
        for (int ks = 0; ks < 4; ks++) {
            uint32_t kb = ks*32 + lkhalf;
            #pragma unroll
            for (int kg = 0; kg < 4; kg++) {
                uint32_t roff = SMEM_SWIZZLE_128B(
                    (uint32_t)((kg*16 + lrow)*128) + kb);
                uint32_t bh_[4], bl_[4];
                ldmx4(bh_, sKh + roff);
                ldmx4(bl_, sKl + roff);
                #pragma unroll
                for (int s2 = 0; s2 < 2; s2++) {
                    int j = 2*kg + s2;
                    mma16816h(s[j], qh[ks], bh_[s2], bh_[s2+2]);
                    mma16816h(s[j], ql[ks], bh_[s2], bh_[s2+2]);
                    mma16816h(s[j], qh[ks], bl_[s2], bl_[s2+2]);
                }
            }
        }

        // mask + scale
        int kt = it * 64;
        uint2 mw0 = *(const uint2*)(mb0 + (kt >> 5));
        uint2 mw1 = *(const uint2*)(mb1 + (kt >> 5));
        #pragma unroll
        for (int j = 0; j < 8; j++) {
            int c = j*8 + tg*2;
            uint32_t w0 = (c & 32) ? mw0.y : mw0.x;
            uint32_t w1 = (c & 32) ? mw1.y : mw1.x;
            int sh = c & 31;
            s[j][0] = ((w0 >> sh) & 1u)     ? s[j][0]*0.125f : -1e30f;
            s[j][1] = ((w0 >> (sh+1)) & 1u) ? s[j][1]*0.125f : -1e30f;
            s[j][2] = ((w1 >> sh) & 1u)     ? s[j][2]*0.125f : -1e30f;
            s[j][3] = ((w1 >> (sh+1)) & 1u) ? s[j][3]*0.125f : -1e30f;
        }

        // row max (quad reduce)
        float tm0 = -1e30f, tm1 = -1e30f;
        #pragma unroll
        for (int j = 0; j < 8; j++) {
            tm0 = fmaxf(tm0, fmaxf(s[j][0], s[j][1]));
            tm1 = fmaxf(tm1, fmaxf(s[j][2], s[j][3]));
        }
        tm0 = fmaxf(tm0, __shfl_xor_sync(0xffffffffu, tm0, 1));
        tm0 = fmaxf(tm0, __shfl_xor_sync(0xffffffffu, tm0, 2));
        tm1 = fmaxf(tm1, __shfl_xor_sync(0xffffffffu, tm1, 1));
        tm1 = fmaxf(tm1, __shfl_xor_sync(0xffffffffu, tm1, 2));

        float M0 = fmaxf(mrun0, tm0), M1 = fmaxf(mrun1, tm1);
        float a0 = fexp2((mrun0 - M0)*LOG2E);
        float a1 = fexp2((mrun1 - M1)*LOG2E);
        mrun0 = M0; mrun1 = M1;

        float ts0 = 0.f, ts1 = 0.f;
        #pragma unroll
        for (int j = 0; j < 8; j++) {
            s[j][0] = fexp2((s[j][0] - M0)*LOG2E);
            s[j][1] = fexp2((s[j][1] - M0)*LOG2E);
            s[j][2] = fexp2((s[j][2] - M1)*LOG2E);
            s[j][3] = fexp2((s[j][3] - M1)*LOG2E);
            ts0 += s[j][0] + s[j][1];
            ts1 += s[j][2] + s[j][3];
        }
        ts0 += __shfl_xor_sync(0xffffffffu, ts0, 1);
        ts0 += __shfl_xor_sync(0xffffffffu, ts0, 2);
        ts1 += __shfl_xor_sync(0xffffffffu, ts1, 1);
        ts1 += __shfl_xor_sync(0xffffffffu, ts1, 2);
        lrun0 = lrun0*a0 + ts0;
        lrun1 = lrun1*a1 + ts1;

        #pragma unroll
        for (int j = 0; j < 8; j++) {
            o[j][0] *= a0; o[j][1] *= a0;
            o[j][2] *= a1; o[j][3] *= a1;
        }

        uint32_t pa[4][4];
        #pragma unroll
        for (int kk = 0; kk < 4; kk++) {
            pa[kk][0] = h2_as_u32(__floats2half2_rn(s[2*kk][0],   s[2*kk][1]));
            pa[kk][1] = h2_as_u32(__floats2half2_rn(s[2*kk][2],   s[2*kk][3]));
            pa[kk][2] = h2_as_u32(__floats2half2_rn(s[2*kk+1][0], s[2*kk+1][1]));
            pa[kk][3] = h2_as_u32(__floats2half2_rn(s[2*kk+1][2], s[2*kk+1][3]));
        }

        #pragma unroll
        for (int kk = 0; kk < 4; kk++) {
            #pragma unroll
            for (int dg = 0; dg < 4; dg++) {
                uint32_t vb[4];
                ldmx4t(vb, sVh + SMEM_SWIZZLE_128B(
                    (uint32_t)((kk*16 + lrow)*128 + dg*32) + lkhalf));
                mma16816h(o[2*dg],   pa[kk], vb[0], vb[1]);
                mma16816h(o[2*dg+1], pa[kk], vb[2], vb[3]);
            }
        }

        buf = (buf + 1 == 3) ? 0 : buf + 1;
        nbuf = (nbuf + 1 == 3) ? 0 : nbuf + 1;
    }

    // finalize: divide by l, split to bf16 hi/lo, store (fused conv_split_o)
    float inv0 = 1.f / fmaxf(lrun0, 1e-9f);
    float inv1 = 1.f / fmaxf(lrun1, 1e-9f);
    size_t i0 = ((size_t)(b*Qn + q0 + r0))*1024 + h*64;
    size_t i1 = ((size_t)(b*Qn + q0 + r1))*1024 + h*64;
    #pragma unroll
    for (int j = 0; j < 8; j++) {
        int d = j*8 + tg*2;
        float v0x = o[j][0]*inv0, v0y = o[j][1]*inv0;
        float v1x = o[j][2]*inv1, v1y = o[j][3]*inv1;
        __nv_bfloat16 h0x = __float2bfloat16(v0x), h0y = __float2bfloat16(v0y);
        __nv_bfloat16 h1x = __float2bfloat16(v1x), h1y = __float2bfloat16(v1y);
        __nv_bfloat162 hh0; hh0.x = h0x; hh0.y = h0y;
        __nv_bfloat162 hh1; hh1.x = h1x; hh1.y = h1y;
        __nv_bfloat162 ll0;
        ll0.x = __float2bfloat16(v0x - __bfloat162float(h0x));
        ll0.y = __float2bfloat16(v0y - __bfloat162float(h0y));
        __nv_bfloat162 ll1;
        ll1.x = __float2bfloat16(v1x - __bfloat162float(h1x));
        ll1.y = __float2bfloat16(v1y - __bfloat162float(h1y));
        *(__nv_bfloat162*)&g_ohi[i0 + d] = hh0;
        *(__nv_bfloat162*)&g_olo[i0 + d] = ll0;
        *(__nv_bfloat162*)&g_ohi[i1 + d] = hh1;
        *(__nv_bfloat162*)&g_olo[i1 + d] = ll1;
    }
}

// ---------------------------------------------------------------------------
extern "C" void kernel_launch(void* const* d_in, const int* in_sizes, int n_in,
                              void* d_out, int out_size)
{
    const float* x    = (const float*)d_in[0];
    const int*   mask = (const int*)d_in[1];
    const float* Wq   = (const float*)d_in[2];
    const float* Wk   = (const float*)d_in[3];
    const float* Wv   = (const float*)d_in[4];
    const float* Wo   = (const float*)d_in[5];
    const float* bo   = (const float*)d_in[6];
    float*       out  = (float*)d_out;

    cudaFuncSetAttribute(qkv_gemm_mma,
                         cudaFuncAttributeMaxDynamicSharedMemorySize, GEMM_SMEM_BYTES);
    cudaFuncSetAttribute(out_gemm_mma,
                         cudaFuncAttributeMaxDynamicSharedMemorySize, GEMM_SMEM_BYTES);
    cudaFuncSetAttribute(attn_mma,
                         cudaFuncAttributeMaxDynamicSharedMemorySize, ATTN_SMEM_BYTES);

    conv_split_x<<<8192, 256>>>(x);
    conv_w<<<dim3(32, 32, 4), 256>>>(Wq, Wk, Wv, Wo);
    pack_mask<<<2048, 256>>>(mask);

    qkv_gemm_mma<<<dim3(24, 64), 256, GEMM_SMEM_BYTES>>>();

    attn_mma<<<dim3(16, 64), 256, ATTN_SMEM_BYTES>>>();

    out_gemm_mma<<<dim3(8, 64), 256, GEMM_SMEM_BYTES>>>(bo, out);
}